// round 3
// baseline (speedup 1.0000x reference)
#include <cuda_runtime.h>
#include <math.h>

#define NB 16
#define NT 2048
#define NC 1024
#define NH 64

// Scratch for Q, K, V projections: [B*T, H] each (8 MB apiece).
__device__ float g_q[NB * NT * NH];
__device__ float g_k[NB * NT * NH];
__device__ float g_v[NB * NT * NH];

// ---------------------------------------------------------------------------
// Kernel 1: fused QKV projection.
// out[row][seg*64+n] = sum_c x[row][c] * w_seg[c][n], seg in {q,k,v}
// BM=64 rows, BN=192 (all three heads), BK=32, 256 threads, 4x12 micro-tile.
// ---------------------------------------------------------------------------
__global__ __launch_bounds__(256) void qkv_kernel(
    const float* __restrict__ x,
    const float* __restrict__ wq,
    const float* __restrict__ wk,
    const float* __restrict__ wv)
{
    __shared__ float xsT[32][64 + 4];  // [kk][row]  (transposed x tile)
    __shared__ float ws[32][192];      // [kk][n]    (fused weight tile)

    const int tid = threadIdx.x;
    const int tx = tid & 15;   // column group (0..15)
    const int ty = tid >> 4;   // row group    (0..15)
    const int row0 = blockIdx.x * 64;

    float acc[4][12];
#pragma unroll
    for (int i = 0; i < 4; i++)
#pragma unroll
        for (int j = 0; j < 12; j++) acc[i][j] = 0.f;

    for (int k0 = 0; k0 < NC; k0 += 32) {
        // ---- load x tile: 64 rows x 32 cols -> transposed store ----
#pragma unroll
        for (int it = 0; it < 2; it++) {
            int f4 = tid + it * 256;          // 512 float4 total
            int r = f4 >> 3;                  // 0..63
            int c4 = f4 & 7;                  // 0..7
            float4 v = *reinterpret_cast<const float4*>(
                &x[(size_t)(row0 + r) * NC + k0 + c4 * 4]);
            xsT[c4 * 4 + 0][r] = v.x;
            xsT[c4 * 4 + 1][r] = v.y;
            xsT[c4 * 4 + 2][r] = v.z;
            xsT[c4 * 4 + 3][r] = v.w;
        }
        // ---- load weight tile: 32 x 192 (three 32x64 slabs) ----
#pragma unroll
        for (int it = 0; it < 6; it++) {
            int f4 = tid + it * 256;          // 1536 float4 total
            int kk = f4 / 48;
            int rem = f4 % 48;
            int seg = rem >> 4;               // 0..2
            int n4 = rem & 15;                // 0..15
            const float* wp = (seg == 0) ? wq : (seg == 1) ? wk : wv;
            float4 v = *reinterpret_cast<const float4*>(
                &wp[(size_t)(k0 + kk) * NH + n4 * 4]);
            *reinterpret_cast<float4*>(&ws[kk][seg * 64 + n4 * 4]) = v;
        }
        __syncthreads();

#pragma unroll 8
        for (int kk = 0; kk < 32; kk++) {
            float4 a = *reinterpret_cast<float4*>(&xsT[kk][ty * 4]);
            float av[4] = {a.x, a.y, a.z, a.w};
            float4 b0 = *reinterpret_cast<float4*>(&ws[kk][0 * 64 + tx * 4]);
            float4 b1 = *reinterpret_cast<float4*>(&ws[kk][1 * 64 + tx * 4]);
            float4 b2 = *reinterpret_cast<float4*>(&ws[kk][2 * 64 + tx * 4]);
            float bv[12] = {b0.x, b0.y, b0.z, b0.w,
                            b1.x, b1.y, b1.z, b1.w,
                            b2.x, b2.y, b2.z, b2.w};
#pragma unroll
            for (int m = 0; m < 4; m++)
#pragma unroll
                for (int n = 0; n < 12; n++)
                    acc[m][n] = fmaf(av[m], bv[n], acc[m][n]);
        }
        __syncthreads();
    }

    // ---- epilogue: write Q, K, V ----
#pragma unroll
    for (int m = 0; m < 4; m++) {
        size_t row = row0 + ty * 4 + m;
        float4 vq = make_float4(acc[m][0], acc[m][1], acc[m][2], acc[m][3]);
        float4 vk = make_float4(acc[m][4], acc[m][5], acc[m][6], acc[m][7]);
        float4 vv = make_float4(acc[m][8], acc[m][9], acc[m][10], acc[m][11]);
        *reinterpret_cast<float4*>(&g_q[row * NH + tx * 4]) = vq;
        *reinterpret_cast<float4*>(&g_k[row * NH + tx * 4]) = vk;
        *reinterpret_cast<float4*>(&g_v[row * NH + tx * 4]) = vv;
    }
}

// ---------------------------------------------------------------------------
// Kernel 2: causal flash attention, fp32.
// BM=64 query rows per CTA, BN=64 keys per iteration, 256 threads.
// Q,K stored transposed in smem -> vectorized operand reads for S = Q K^T.
// Online softmax: one thread per row (threads 0..63).
// O accumulated in registers: thread (tx,ty) owns rows ty*4.. cols tx*4..
// ---------------------------------------------------------------------------
#define SROW 68                    // 64 + 4 pad (keeps float4 alignment)
#define OFF_QT 0
#define OFF_KT (64 * SROW)
#define OFF_V  (2 * 64 * SROW)
#define OFF_S  (3 * 64 * SROW)
#define OFF_M  (4 * 64 * SROW)
#define OFF_L  (OFF_M + 64)
#define OFF_C  (OFF_L + 64)
#define SMEM_FLOATS (OFF_C + 64)   // 17600 floats = 70400 bytes

__global__ __launch_bounds__(256) void attn_kernel(float* __restrict__ out)
{
    extern __shared__ float sm[];
    float* qT = sm + OFF_QT;   // [h][i]
    float* kT = sm + OFF_KT;   // [h][j]
    float* vS = sm + OFF_V;    // [j][h]
    float* sS = sm + OFF_S;    // [i][j]
    float* rowm = sm + OFF_M;
    float* rowl = sm + OFF_L;
    float* rowc = sm + OFF_C;

    const int tid = threadIdx.x;
    const int tx = tid & 15;
    const int ty = tid >> 4;
    const int b = blockIdx.y;
    const int qt = gridDim.x - 1 - blockIdx.x;  // heavy tiles first
    const int qs = qt * 64;

    // ---- load Q tile transposed ----
    const float* qg = g_q + ((size_t)b * NT + qs) * NH;
#pragma unroll
    for (int it = 0; it < 4; it++) {
        int f4 = tid + it * 256;       // 1024 float4
        int r = f4 >> 4;               // 0..63
        int h4 = f4 & 15;              // 0..15
        float4 v = *reinterpret_cast<const float4*>(&qg[r * NH + h4 * 4]);
        qT[(h4 * 4 + 0) * SROW + r] = v.x;
        qT[(h4 * 4 + 1) * SROW + r] = v.y;
        qT[(h4 * 4 + 2) * SROW + r] = v.z;
        qT[(h4 * 4 + 3) * SROW + r] = v.w;
    }
    if (tid < 64) { rowm[tid] = -1e30f; rowl[tid] = 0.f; }

    float o[4][4];
#pragma unroll
    for (int m = 0; m < 4; m++)
#pragma unroll
        for (int n = 0; n < 4; n++) o[m][n] = 0.f;

    const int ntiles = qt + 1;
    for (int st = 0; st < ntiles; st++) {
        const int s0 = st * 64;
        const float* kg = g_k + ((size_t)b * NT + s0) * NH;
        const float* vg = g_v + ((size_t)b * NT + s0) * NH;

        __syncthreads();  // protect kT/vS/sS from previous iteration readers
        // ---- load K (transposed) and V tiles ----
#pragma unroll
        for (int it = 0; it < 4; it++) {
            int f4 = tid + it * 256;
            int j = f4 >> 4;
            int h4 = f4 & 15;
            float4 kv = *reinterpret_cast<const float4*>(&kg[j * NH + h4 * 4]);
            kT[(h4 * 4 + 0) * SROW + j] = kv.x;
            kT[(h4 * 4 + 1) * SROW + j] = kv.y;
            kT[(h4 * 4 + 2) * SROW + j] = kv.z;
            kT[(h4 * 4 + 3) * SROW + j] = kv.w;
            float4 vv = *reinterpret_cast<const float4*>(&vg[j * NH + h4 * 4]);
            *reinterpret_cast<float4*>(&vS[j * SROW + h4 * 4]) = vv;
        }
        __syncthreads();

        // ---- S = Q K^T (scaled, masked on diagonal tile) ----
        float sacc[4][4];
#pragma unroll
        for (int m = 0; m < 4; m++)
#pragma unroll
            for (int n = 0; n < 4; n++) sacc[m][n] = 0.f;

#pragma unroll 8
        for (int h = 0; h < NH; h++) {
            float4 a = *reinterpret_cast<float4*>(&qT[h * SROW + ty * 4]);
            float4 bb = *reinterpret_cast<float4*>(&kT[h * SROW + tx * 4]);
            float av[4] = {a.x, a.y, a.z, a.w};
            float bv[4] = {bb.x, bb.y, bb.z, bb.w};
#pragma unroll
            for (int m = 0; m < 4; m++)
#pragma unroll
                for (int n = 0; n < 4; n++)
                    sacc[m][n] = fmaf(av[m], bv[n], sacc[m][n]);
        }
        const bool diag = (st == ntiles - 1);
#pragma unroll
        for (int m = 0; m < 4; m++) {
            int i = ty * 4 + m;
#pragma unroll
            for (int n = 0; n < 4; n++) {
                int j = tx * 4 + n;
                float v = sacc[m][n] * 0.125f;
                if (diag && (j > i)) v = -1e30f;
                sS[i * SROW + j] = v;
            }
        }
        __syncthreads();

        // ---- online softmax: one thread per row ----
        if (tid < 64) {
            int r = tid;
            float oldm = rowm[r];
            float rmax = -1e30f;
#pragma unroll
            for (int j4 = 0; j4 < 16; j4++) {
                float4 p = *reinterpret_cast<float4*>(&sS[r * SROW + j4 * 4]);
                rmax = fmaxf(rmax, fmaxf(fmaxf(p.x, p.y), fmaxf(p.z, p.w)));
            }
            float newm = fmaxf(oldm, rmax);
            float corr = __expf(oldm - newm);
            float sum = 0.f;
#pragma unroll 4
            for (int j = 0; j < 64; j++) {
                float p = __expf(sS[r * SROW + j] - newm);
                sS[r * SROW + j] = p;
                sum += p;
            }
            rowl[r] = rowl[r] * corr + sum;
            rowm[r] = newm;
            rowc[r] = corr;
        }
        __syncthreads();

        // ---- O = O*corr + P V ----
        float c0 = rowc[ty * 4 + 0];
        float c1 = rowc[ty * 4 + 1];
        float c2 = rowc[ty * 4 + 2];
        float c3 = rowc[ty * 4 + 3];
#pragma unroll
        for (int n = 0; n < 4; n++) {
            o[0][n] *= c0; o[1][n] *= c1; o[2][n] *= c2; o[3][n] *= c3;
        }
#pragma unroll 8
        for (int j = 0; j < 64; j++) {
            float4 vv = *reinterpret_cast<float4*>(&vS[j * SROW + tx * 4]);
            float vvv[4] = {vv.x, vv.y, vv.z, vv.w};
            float p0 = sS[(ty * 4 + 0) * SROW + j];
            float p1 = sS[(ty * 4 + 1) * SROW + j];
            float p2 = sS[(ty * 4 + 2) * SROW + j];
            float p3 = sS[(ty * 4 + 3) * SROW + j];
#pragma unroll
            for (int n = 0; n < 4; n++) {
                o[0][n] = fmaf(p0, vvv[n], o[0][n]);
                o[1][n] = fmaf(p1, vvv[n], o[1][n]);
                o[2][n] = fmaf(p2, vvv[n], o[2][n]);
                o[3][n] = fmaf(p3, vvv[n], o[3][n]);
            }
        }
    }

    __syncthreads();  // rowl stable
    // ---- epilogue: out = O / l ----
#pragma unroll
    for (int m = 0; m < 4; m++) {
        int i = ty * 4 + m;
        float inv = 1.0f / rowl[i];
        float4 r = make_float4(o[m][0] * inv, o[m][1] * inv,
                               o[m][2] * inv, o[m][3] * inv);
        *reinterpret_cast<float4*>(
            &out[((size_t)b * NT + qs + i) * NH + tx * 4]) = r;
    }
}

// ---------------------------------------------------------------------------
extern "C" void kernel_launch(void* const* d_in, const int* in_sizes, int n_in,
                              void* d_out, int out_size)
{
    const float* x  = (const float*)d_in[0];
    const float* wq = (const float*)d_in[1];
    const float* wk = (const float*)d_in[2];
    const float* wv = (const float*)d_in[3];
    float* out = (float*)d_out;

    qkv_kernel<<<(NB * NT) / 64, 256>>>(x, wq, wk, wv);

    const int smem_bytes = SMEM_FLOATS * sizeof(float);  // 70400 B
    cudaFuncSetAttribute(attn_kernel,
                         cudaFuncAttributeMaxDynamicSharedMemorySize,
                         smem_bytes);
    attn_kernel<<<dim3(NT / 64, NB), 256, smem_bytes>>>(out);
}

// round 5
// speedup vs baseline: 1.2891x; 1.2891x over previous
#include <cuda_runtime.h>
#include <cuda_bf16.h>
#include <math.h>
#include <stdint.h>

#define NB 16
#define NT 2048
#define NC 1024
#define NH 64

// Scratch for Q, K, V projections: [B*T, H] each (8 MB apiece).
__device__ float g_q[NB * NT * NH];
__device__ float g_k[NB * NT * NH];
__device__ float g_v[NB * NT * NH];

__device__ __forceinline__ uint32_t pack_bf16(float a, float b) {
    __nv_bfloat162 t = __floats2bfloat162_rn(a, b);
    return *reinterpret_cast<uint32_t*>(&t);
}

// mma.sync m16n8k16 bf16 (baseline PTX, works on plain sm_103 target)
#define MMA_BF16(c, a0, a1, a2, a3, b0, b1)                                \
    asm volatile(                                                          \
        "mma.sync.aligned.m16n8k16.row.col.f32.bf16.bf16.f32 "             \
        "{%0,%1,%2,%3}, {%4,%5,%6,%7}, {%8,%9}, {%0,%1,%2,%3};"            \
        : "+f"((c)[0]), "+f"((c)[1]), "+f"((c)[2]), "+f"((c)[3])           \
        : "r"(a0), "r"(a1), "r"(a2), "r"(a3), "r"(b0), "r"(b1))

// ===========================================================================
// Kernel 1: fused QKV projection, bf16 split-precision mma.sync.
// C[32768 x 192] = X[32768 x 1024] * W[1024 x 192]
// CTA tile: M=128, N=96 (grid 256 x 2). 8 warps = 4(m) x 2(n).
// Per warp: 32 x 48 = 2 x 6 m16n8k16 tiles. BK=32 per iter, double-buffered.
// smem row stride = 20 uint32 (80B) -> conflict-free fragment LDS.
// ===========================================================================
#define KST 20                      // uint32 stride per logical row (16 used)
#define A_H_OFF 0                   // 128 rows
#define A_L_OFF (128 * KST)
#define B_H_OFF (2 * 128 * KST)    // 96 rows
#define B_L_OFF (2 * 128 * KST + 96 * KST)
#define QKV_BUF_U32 (2 * 128 * KST + 2 * 96 * KST)   // 8960
#define QKV_SMEM_BYTES (2 * QKV_BUF_U32 * 4)         // 71680

__global__ __launch_bounds__(256) void qkv_mma_kernel(
    const float* __restrict__ x,
    const float* __restrict__ wq,
    const float* __restrict__ wk,
    const float* __restrict__ wv)
{
    extern __shared__ char dynsm[];
    uint32_t* smu = reinterpret_cast<uint32_t*>(dynsm);

    const int tid = threadIdx.x;
    const int warp = tid >> 5;
    const int lane = tid & 31;
    const int g = lane >> 2;        // group row 0..7
    const int t4 = lane & 3;        // thread-in-group 0..3
    const int wm = warp & 3;        // 0..3
    const int wn = warp >> 2;       // 0..1
    const int m_base = wm * 32;
    const int n_base = wn * 48;
    const int row0 = blockIdx.x * 128;
    const int col0 = blockIdx.y * 96;

    float acc[2][6][4];
#pragma unroll
    for (int mt = 0; mt < 2; mt++)
#pragma unroll
        for (int nt = 0; nt < 6; nt++)
#pragma unroll
            for (int i = 0; i < 4; i++) acc[mt][nt][i] = 0.f;

    float4 ast[4];
    float bst[3][4];

    // ---- gmem -> regs (A: 128x32 fp32; B: 96n x 32k gathered from w[k][n]) --
    auto ldg_tiles = [&](int k0) {
#pragma unroll
        for (int it = 0; it < 4; it++) {
            int f4 = tid + it * 256;          // 1024 float4, 8 per row
            int r = f4 >> 3;
            int c4 = f4 & 7;
            ast[it] = *reinterpret_cast<const float4*>(
                &x[(size_t)(row0 + r) * NC + k0 + c4 * 4]);
        }
#pragma unroll
        for (int it = 0; it < 3; it++) {
            int p = tid + it * 256;           // 768 tasks = 96n x 8kp
            int n_g = p % 96;
            int kp = p / 96;
            int n_global = col0 + n_g;
            int seg = n_global >> 6;
            int nc = n_global & 63;
            const float* wp = (seg == 0) ? wq : (seg == 1) ? wk : wv;
            const float* src = wp + (size_t)(k0 + kp * 4) * NH + nc;
#pragma unroll
            for (int j = 0; j < 4; j++) bst[it][j] = src[j * NH];
        }
    };

    // ---- regs -> smem (bf16 hi/lo split) ----
    auto sts_tiles = [&](int buf) {
        uint32_t* base = smu + buf * QKV_BUF_U32;
#pragma unroll
        for (int it = 0; it < 4; it++) {
            int f4 = tid + it * 256;
            int r = f4 >> 3;
            int c4 = f4 & 7;
            float4 v = ast[it];
            float h0 = __bfloat162float(__float2bfloat16(v.x));
            float h1 = __bfloat162float(__float2bfloat16(v.y));
            float h2 = __bfloat162float(__float2bfloat16(v.z));
            float h3 = __bfloat162float(__float2bfloat16(v.w));
            int idx = r * KST + c4 * 2;
            base[A_H_OFF + idx + 0] = pack_bf16(h0, h1);
            base[A_H_OFF + idx + 1] = pack_bf16(h2, h3);
            base[A_L_OFF + idx + 0] = pack_bf16(v.x - h0, v.y - h1);
            base[A_L_OFF + idx + 1] = pack_bf16(v.z - h2, v.w - h3);
        }
#pragma unroll
        for (int it = 0; it < 3; it++) {
            int p = tid + it * 256;
            int n_g = p % 96;
            int kp = p / 96;
            float v0 = bst[it][0], v1 = bst[it][1], v2 = bst[it][2], v3 = bst[it][3];
            float h0 = __bfloat162float(__float2bfloat16(v0));
            float h1 = __bfloat162float(__float2bfloat16(v1));
            float h2 = __bfloat162float(__float2bfloat16(v2));
            float h3 = __bfloat162float(__float2bfloat16(v3));
            int idx = n_g * KST + kp * 2;
            base[B_H_OFF + idx + 0] = pack_bf16(h0, h1);
            base[B_H_OFF + idx + 1] = pack_bf16(h2, h3);
            base[B_L_OFF + idx + 0] = pack_bf16(v0 - h0, v1 - h1);
            base[B_L_OFF + idx + 1] = pack_bf16(v2 - h2, v3 - h3);
        }
    };

    // ---- compute one BK=32 slab from smem buffer ----
    auto compute = [&](int buf) {
        uint32_t* base = smu + buf * QKV_BUF_U32;
        const uint32_t* Ah = base + A_H_OFF;
        const uint32_t* Al = base + A_L_OFF;
        const uint32_t* Bh = base + B_H_OFF;
        const uint32_t* Bl = base + B_L_OFF;
#pragma unroll
        for (int ks = 0; ks < 2; ks++) {
            uint32_t bh[6][2], bl[6][2];
#pragma unroll
            for (int nt = 0; nt < 6; nt++) {
                int nrow = n_base + nt * 8 + g;
                const uint32_t* bp = Bh + nrow * KST + ks * 8 + t4;
                bh[nt][0] = bp[0];
                bh[nt][1] = bp[4];
                const uint32_t* bp2 = Bl + nrow * KST + ks * 8 + t4;
                bl[nt][0] = bp2[0];
                bl[nt][1] = bp2[4];
            }
#pragma unroll
            for (int mt = 0; mt < 2; mt++) {
                int arow = m_base + mt * 16 + g;
                const uint32_t* ap = Ah + arow * KST + ks * 8 + t4;
                uint32_t ah0 = ap[0], ah1 = ap[8 * KST], ah2 = ap[4], ah3 = ap[8 * KST + 4];
                const uint32_t* ap2 = Al + arow * KST + ks * 8 + t4;
                uint32_t al0 = ap2[0], al1 = ap2[8 * KST], al2 = ap2[4], al3 = ap2[8 * KST + 4];
#pragma unroll
                for (int nt = 0; nt < 6; nt++) {
                    MMA_BF16(acc[mt][nt], ah0, ah1, ah2, ah3, bh[nt][0], bh[nt][1]);
                    MMA_BF16(acc[mt][nt], ah0, ah1, ah2, ah3, bl[nt][0], bl[nt][1]);
                    MMA_BF16(acc[mt][nt], al0, al1, al2, al3, bh[nt][0], bh[nt][1]);
                }
            }
        }
    };

    // ---- main loop: 32 K-slabs, double-buffered ----
    ldg_tiles(0);
    sts_tiles(0);
    __syncthreads();
    const int NIT = NC / 32;  // 32
    for (int tI = 0; tI < NIT; tI++) {
        if (tI + 1 < NIT) ldg_tiles((tI + 1) * 32);
        compute(tI & 1);
        if (tI + 1 < NIT) sts_tiles((tI + 1) & 1);
        __syncthreads();
    }

    // ---- epilogue ----
#pragma unroll
    for (int mt = 0; mt < 2; mt++) {
#pragma unroll
        for (int nt = 0; nt < 6; nt++) {
            int n_global = col0 + n_base + nt * 8 + t4 * 2;
            int seg = n_global >> 6;
            int nc = n_global & 63;
            float* dstb = (seg == 0) ? g_q : (seg == 1) ? g_k : g_v;
            size_t r0 = (size_t)row0 + m_base + mt * 16 + g;
            *reinterpret_cast<float2*>(&dstb[r0 * NH + nc]) =
                make_float2(acc[mt][nt][0], acc[mt][nt][1]);
            *reinterpret_cast<float2*>(&dstb[(r0 + 8) * NH + nc]) =
                make_float2(acc[mt][nt][2], acc[mt][nt][3]);
        }
    }
}

// ===========================================================================
// Kernel 2: causal flash attention, fp32 (softmax parallelized 4 threads/row)
// ===========================================================================
#define SROW 68
#define OFF_QT 0
#define OFF_KT (64 * SROW)
#define OFF_V  (2 * 64 * SROW)
#define OFF_S  (3 * 64 * SROW)
#define OFF_M  (4 * 64 * SROW)
#define OFF_L  (OFF_M + 64)
#define OFF_C  (OFF_L + 64)
#define SMEM_FLOATS (OFF_C + 64)

__global__ __launch_bounds__(256) void attn_kernel(float* __restrict__ out)
{
    extern __shared__ char dynsm[];
    float* sm = reinterpret_cast<float*>(dynsm);
    float* qT = sm + OFF_QT;
    float* kT = sm + OFF_KT;
    float* vS = sm + OFF_V;
    float* sS = sm + OFF_S;
    float* rowm = sm + OFF_M;
    float* rowl = sm + OFF_L;
    float* rowc = sm + OFF_C;

    const int tid = threadIdx.x;
    const int tx = tid & 15;
    const int ty = tid >> 4;
    const int b = blockIdx.y;
    const int qt = gridDim.x - 1 - blockIdx.x;  // heavy tiles first
    const int qs = qt * 64;

    const float* qg = g_q + ((size_t)b * NT + qs) * NH;
#pragma unroll
    for (int it = 0; it < 4; it++) {
        int f4 = tid + it * 256;
        int r = f4 >> 4;
        int h4 = f4 & 15;
        float4 v = *reinterpret_cast<const float4*>(&qg[r * NH + h4 * 4]);
        qT[(h4 * 4 + 0) * SROW + r] = v.x;
        qT[(h4 * 4 + 1) * SROW + r] = v.y;
        qT[(h4 * 4 + 2) * SROW + r] = v.z;
        qT[(h4 * 4 + 3) * SROW + r] = v.w;
    }
    if (tid < 64) { rowm[tid] = -1e30f; rowl[tid] = 0.f; }

    float o[4][4];
#pragma unroll
    for (int m = 0; m < 4; m++)
#pragma unroll
        for (int n = 0; n < 4; n++) o[m][n] = 0.f;

    const int ntiles = qt + 1;
    for (int st = 0; st < ntiles; st++) {
        const int s0 = st * 64;
        const float* kg = g_k + ((size_t)b * NT + s0) * NH;
        const float* vg = g_v + ((size_t)b * NT + s0) * NH;

        __syncthreads();
#pragma unroll
        for (int it = 0; it < 4; it++) {
            int f4 = tid + it * 256;
            int j = f4 >> 4;
            int h4 = f4 & 15;
            float4 kv = *reinterpret_cast<const float4*>(&kg[j * NH + h4 * 4]);
            kT[(h4 * 4 + 0) * SROW + j] = kv.x;
            kT[(h4 * 4 + 1) * SROW + j] = kv.y;
            kT[(h4 * 4 + 2) * SROW + j] = kv.z;
            kT[(h4 * 4 + 3) * SROW + j] = kv.w;
            float4 vv = *reinterpret_cast<const float4*>(&vg[j * NH + h4 * 4]);
            *reinterpret_cast<float4*>(&vS[j * SROW + h4 * 4]) = vv;
        }
        __syncthreads();

        float sacc[4][4];
#pragma unroll
        for (int m = 0; m < 4; m++)
#pragma unroll
            for (int n = 0; n < 4; n++) sacc[m][n] = 0.f;

#pragma unroll 8
        for (int h = 0; h < NH; h++) {
            float4 a = *reinterpret_cast<float4*>(&qT[h * SROW + ty * 4]);
            float4 bb = *reinterpret_cast<float4*>(&kT[h * SROW + tx * 4]);
            float av[4] = {a.x, a.y, a.z, a.w};
            float bv[4] = {bb.x, bb.y, bb.z, bb.w};
#pragma unroll
            for (int m = 0; m < 4; m++)
#pragma unroll
                for (int n = 0; n < 4; n++)
                    sacc[m][n] = fmaf(av[m], bv[n], sacc[m][n]);
        }
        const bool diag = (st == ntiles - 1);
#pragma unroll
        for (int m = 0; m < 4; m++) {
            int i = ty * 4 + m;
#pragma unroll
            for (int n = 0; n < 4; n++) {
                int j = tx * 4 + n;
                float v = sacc[m][n] * 0.125f;
                if (diag && (j > i)) v = -1e30f;
                sS[i * SROW + j] = v;
            }
        }
        __syncthreads();

        // online softmax: 4 threads per row
        {
            int r = tid >> 2;
            int qq = tid & 3;
            float oldm = rowm[r];
            float rmax = -1e30f;
#pragma unroll
            for (int j4 = 0; j4 < 4; j4++) {
                float4 p = *reinterpret_cast<float4*>(&sS[r * SROW + qq * 16 + j4 * 4]);
                rmax = fmaxf(rmax, fmaxf(fmaxf(p.x, p.y), fmaxf(p.z, p.w)));
            }
            rmax = fmaxf(rmax, __shfl_xor_sync(0xffffffffu, rmax, 1));
            rmax = fmaxf(rmax, __shfl_xor_sync(0xffffffffu, rmax, 2));
            float newm = fmaxf(oldm, rmax);
            float sum = 0.f;
#pragma unroll
            for (int j = 0; j < 16; j++) {
                float p = __expf(sS[r * SROW + qq * 16 + j] - newm);
                sS[r * SROW + qq * 16 + j] = p;
                sum += p;
            }
            sum += __shfl_xor_sync(0xffffffffu, sum, 1);
            sum += __shfl_xor_sync(0xffffffffu, sum, 2);
            if (qq == 0) {
                float corr = __expf(oldm - newm);
                rowl[r] = rowl[r] * corr + sum;
                rowm[r] = newm;
                rowc[r] = corr;
            }
        }
        __syncthreads();

        float c0 = rowc[ty * 4 + 0];
        float c1 = rowc[ty * 4 + 1];
        float c2 = rowc[ty * 4 + 2];
        float c3 = rowc[ty * 4 + 3];
#pragma unroll
        for (int n = 0; n < 4; n++) {
            o[0][n] *= c0; o[1][n] *= c1; o[2][n] *= c2; o[3][n] *= c3;
        }
#pragma unroll 8
        for (int j = 0; j < 64; j++) {
            float4 vv = *reinterpret_cast<float4*>(&vS[j * SROW + tx * 4]);
            float vvv[4] = {vv.x, vv.y, vv.z, vv.w};
            float p0 = sS[(ty * 4 + 0) * SROW + j];
            float p1 = sS[(ty * 4 + 1) * SROW + j];
            float p2 = sS[(ty * 4 + 2) * SROW + j];
            float p3 = sS[(ty * 4 + 3) * SROW + j];
#pragma unroll
            for (int n = 0; n < 4; n++) {
                o[0][n] = fmaf(p0, vvv[n], o[0][n]);
                o[1][n] = fmaf(p1, vvv[n], o[1][n]);
                o[2][n] = fmaf(p2, vvv[n], o[2][n]);
                o[3][n] = fmaf(p3, vvv[n], o[3][n]);
            }
        }
    }

    __syncthreads();
#pragma unroll
    for (int m = 0; m < 4; m++) {
        int i = ty * 4 + m;
        float inv = 1.0f / rowl[i];
        float4 r = make_float4(o[m][0] * inv, o[m][1] * inv,
                               o[m][2] * inv, o[m][3] * inv);
        *reinterpret_cast<float4*>(
            &out[((size_t)b * NT + qs + i) * NH + tx * 4]) = r;
    }
}

// ===========================================================================
extern "C" void kernel_launch(void* const* d_in, const int* in_sizes, int n_in,
                              void* d_out, int out_size)
{
    const float* x  = (const float*)d_in[0];
    const float* wq = (const float*)d_in[1];
    const float* wk = (const float*)d_in[2];
    const float* wv = (const float*)d_in[3];
    float* out = (float*)d_out;

    cudaFuncSetAttribute(qkv_mma_kernel,
                         cudaFuncAttributeMaxDynamicSharedMemorySize,
                         QKV_SMEM_BYTES);
    qkv_mma_kernel<<<dim3(256, 2), 256, QKV_SMEM_BYTES>>>(x, wq, wk, wv);

    const int attn_smem = SMEM_FLOATS * sizeof(float);
    cudaFuncSetAttribute(attn_kernel,
                         cudaFuncAttributeMaxDynamicSharedMemorySize,
                         attn_smem);
    attn_kernel<<<dim3(NT / 64, NB), 256, attn_smem>>>(out);
}

// round 6
// speedup vs baseline: 1.9890x; 1.5430x over previous
#include <cuda_runtime.h>
#include <cuda_bf16.h>
#include <math.h>
#include <stdint.h>

#define NB 16
#define NT 2048
#define NC 1024
#define NH 64

// Scratch for Q, K, V projections: [B*T, H] each (8 MB apiece).
__device__ float g_q[NB * NT * NH];
__device__ float g_k[NB * NT * NH];
__device__ float g_v[NB * NT * NH];

__device__ __forceinline__ uint32_t pack_bf16(float a, float b) {
    __nv_bfloat162 t = __floats2bfloat162_rn(a, b);
    return *reinterpret_cast<uint32_t*>(&t);
}

// mma.sync m16n8k16 bf16 (baseline PTX, works on plain sm_103 target)
#define MMA_BF16(c, a0, a1, a2, a3, b0, b1)                                \
    asm volatile(                                                          \
        "mma.sync.aligned.m16n8k16.row.col.f32.bf16.bf16.f32 "             \
        "{%0,%1,%2,%3}, {%4,%5,%6,%7}, {%8,%9}, {%0,%1,%2,%3};"            \
        : "+f"((c)[0]), "+f"((c)[1]), "+f"((c)[2]), "+f"((c)[3])           \
        : "r"(a0), "r"(a1), "r"(a2), "r"(a3), "r"(b0), "r"(b1))

// ===========================================================================
// Kernel 1: fused QKV projection, bf16 split-precision mma.sync. (R4, passing)
// ===========================================================================
#define KST 20
#define A_H_OFF 0
#define A_L_OFF (128 * KST)
#define B_H_OFF (2 * 128 * KST)
#define B_L_OFF (2 * 128 * KST + 96 * KST)
#define QKV_BUF_U32 (2 * 128 * KST + 2 * 96 * KST)
#define QKV_SMEM_BYTES (2 * QKV_BUF_U32 * 4)

__global__ __launch_bounds__(256) void qkv_mma_kernel(
    const float* __restrict__ x,
    const float* __restrict__ wq,
    const float* __restrict__ wk,
    const float* __restrict__ wv)
{
    extern __shared__ char dynsm[];
    uint32_t* smu = reinterpret_cast<uint32_t*>(dynsm);

    const int tid = threadIdx.x;
    const int warp = tid >> 5;
    const int lane = tid & 31;
    const int g = lane >> 2;
    const int t4 = lane & 3;
    const int wm = warp & 3;
    const int wn = warp >> 2;
    const int m_base = wm * 32;
    const int n_base = wn * 48;
    const int row0 = blockIdx.x * 128;
    const int col0 = blockIdx.y * 96;

    float acc[2][6][4];
#pragma unroll
    for (int mt = 0; mt < 2; mt++)
#pragma unroll
        for (int nt = 0; nt < 6; nt++)
#pragma unroll
            for (int i = 0; i < 4; i++) acc[mt][nt][i] = 0.f;

    float4 ast[4];
    float bst[3][4];

    auto ldg_tiles = [&](int k0) {
#pragma unroll
        for (int it = 0; it < 4; it++) {
            int f4 = tid + it * 256;
            int r = f4 >> 3;
            int c4 = f4 & 7;
            ast[it] = *reinterpret_cast<const float4*>(
                &x[(size_t)(row0 + r) * NC + k0 + c4 * 4]);
        }
#pragma unroll
        for (int it = 0; it < 3; it++) {
            int p = tid + it * 256;
            int n_g = p % 96;
            int kp = p / 96;
            int n_global = col0 + n_g;
            int seg = n_global >> 6;
            int nc = n_global & 63;
            const float* wp = (seg == 0) ? wq : (seg == 1) ? wk : wv;
            const float* src = wp + (size_t)(k0 + kp * 4) * NH + nc;
#pragma unroll
            for (int j = 0; j < 4; j++) bst[it][j] = src[j * NH];
        }
    };

    auto sts_tiles = [&](int buf) {
        uint32_t* base = smu + buf * QKV_BUF_U32;
#pragma unroll
        for (int it = 0; it < 4; it++) {
            int f4 = tid + it * 256;
            int r = f4 >> 3;
            int c4 = f4 & 7;
            float4 v = ast[it];
            float h0 = __bfloat162float(__float2bfloat16(v.x));
            float h1 = __bfloat162float(__float2bfloat16(v.y));
            float h2 = __bfloat162float(__float2bfloat16(v.z));
            float h3 = __bfloat162float(__float2bfloat16(v.w));
            int idx = r * KST + c4 * 2;
            base[A_H_OFF + idx + 0] = pack_bf16(h0, h1);
            base[A_H_OFF + idx + 1] = pack_bf16(h2, h3);
            base[A_L_OFF + idx + 0] = pack_bf16(v.x - h0, v.y - h1);
            base[A_L_OFF + idx + 1] = pack_bf16(v.z - h2, v.w - h3);
        }
#pragma unroll
        for (int it = 0; it < 3; it++) {
            int p = tid + it * 256;
            int n_g = p % 96;
            int kp = p / 96;
            float v0 = bst[it][0], v1 = bst[it][1], v2 = bst[it][2], v3 = bst[it][3];
            float h0 = __bfloat162float(__float2bfloat16(v0));
            float h1 = __bfloat162float(__float2bfloat16(v1));
            float h2 = __bfloat162float(__float2bfloat16(v2));
            float h3 = __bfloat162float(__float2bfloat16(v3));
            int idx = n_g * KST + kp * 2;
            base[B_H_OFF + idx + 0] = pack_bf16(h0, h1);
            base[B_H_OFF + idx + 1] = pack_bf16(h2, h3);
            base[B_L_OFF + idx + 0] = pack_bf16(v0 - h0, v1 - h1);
            base[B_L_OFF + idx + 1] = pack_bf16(v2 - h2, v3 - h3);
        }
    };

    auto compute = [&](int buf) {
        uint32_t* base = smu + buf * QKV_BUF_U32;
        const uint32_t* Ah = base + A_H_OFF;
        const uint32_t* Al = base + A_L_OFF;
        const uint32_t* Bh = base + B_H_OFF;
        const uint32_t* Bl = base + B_L_OFF;
#pragma unroll
        for (int ks = 0; ks < 2; ks++) {
            uint32_t bh[6][2], bl[6][2];
#pragma unroll
            for (int nt = 0; nt < 6; nt++) {
                int nrow = n_base + nt * 8 + g;
                const uint32_t* bp = Bh + nrow * KST + ks * 8 + t4;
                bh[nt][0] = bp[0];
                bh[nt][1] = bp[4];
                const uint32_t* bp2 = Bl + nrow * KST + ks * 8 + t4;
                bl[nt][0] = bp2[0];
                bl[nt][1] = bp2[4];
            }
#pragma unroll
            for (int mt = 0; mt < 2; mt++) {
                int arow = m_base + mt * 16 + g;
                const uint32_t* ap = Ah + arow * KST + ks * 8 + t4;
                uint32_t ah0 = ap[0], ah1 = ap[8 * KST], ah2 = ap[4], ah3 = ap[8 * KST + 4];
                const uint32_t* ap2 = Al + arow * KST + ks * 8 + t4;
                uint32_t al0 = ap2[0], al1 = ap2[8 * KST], al2 = ap2[4], al3 = ap2[8 * KST + 4];
#pragma unroll
                for (int nt = 0; nt < 6; nt++) {
                    MMA_BF16(acc[mt][nt], ah0, ah1, ah2, ah3, bh[nt][0], bh[nt][1]);
                    MMA_BF16(acc[mt][nt], ah0, ah1, ah2, ah3, bl[nt][0], bl[nt][1]);
                    MMA_BF16(acc[mt][nt], al0, al1, al2, al3, bh[nt][0], bh[nt][1]);
                }
            }
        }
    };

    ldg_tiles(0);
    sts_tiles(0);
    __syncthreads();
    const int NIT = NC / 32;
    for (int tI = 0; tI < NIT; tI++) {
        if (tI + 1 < NIT) ldg_tiles((tI + 1) * 32);
        compute(tI & 1);
        if (tI + 1 < NIT) sts_tiles((tI + 1) & 1);
        __syncthreads();
    }

#pragma unroll
    for (int mt = 0; mt < 2; mt++) {
#pragma unroll
        for (int nt = 0; nt < 6; nt++) {
            int n_global = col0 + n_base + nt * 8 + t4 * 2;
            int seg = n_global >> 6;
            int nc = n_global & 63;
            float* dstb = (seg == 0) ? g_q : (seg == 1) ? g_k : g_v;
            size_t r0 = (size_t)row0 + m_base + mt * 16 + g;
            *reinterpret_cast<float2*>(&dstb[r0 * NH + nc]) =
                make_float2(acc[mt][nt][0], acc[mt][nt][1]);
            *reinterpret_cast<float2*>(&dstb[(r0 + 8) * NH + nc]) =
                make_float2(acc[mt][nt][2], acc[mt][nt][3]);
        }
    }
}

// ===========================================================================
// Kernel 2: causal flash attention on mma.sync bf16 (split precision).
// BM=64 rows/CTA, BN=64 keys/iter, 4 warps, each warp owns 16 full rows.
// S and O accumulators + softmax state all register-resident; P never
// leaves registers (S-frag layout == A-frag layout for the PV MMA).
// ===========================================================================
#define AST 36                      // u32 stride per 64-elem bf16 row
#define QH_OFF 0
#define QL_OFF (64 * AST)
#define KH_OFF (2 * 64 * AST)
#define KL_OFF (3 * 64 * AST)
#define VH_OFF (4 * 64 * AST)       // transposed: [h][s]
#define VL_OFF (5 * 64 * AST)
#define ATTN_SMEM_U32 (6 * 64 * AST)
#define ATTN_SMEM_BYTES (ATTN_SMEM_U32 * 4)   // 55296

__global__ __launch_bounds__(128) void attn_mma_kernel(float* __restrict__ out)
{
    extern __shared__ char dynsm[];
    uint32_t* smu = reinterpret_cast<uint32_t*>(dynsm);

    const int tid = threadIdx.x;
    const int warp = tid >> 5;
    const int lane = tid & 31;
    const int g = lane >> 2;
    const int t4 = lane & 3;
    const int m_base = warp * 16;
    const int b = blockIdx.y;
    const int qt = gridDim.x - 1 - blockIdx.x;   // heavy tiles first
    const int qs = qt * 64;

    // ---- load Q tile -> smem (bf16 hi/lo, [i][h]) ----
    const float* qg = g_q + ((size_t)b * NT + qs) * NH;
#pragma unroll
    for (int it = 0; it < 8; it++) {
        int f4 = tid + it * 128;
        int r = f4 >> 4;
        int h4 = f4 & 15;
        float4 v = *reinterpret_cast<const float4*>(&qg[r * NH + h4 * 4]);
        float h0 = __bfloat162float(__float2bfloat16(v.x));
        float h1 = __bfloat162float(__float2bfloat16(v.y));
        float h2 = __bfloat162float(__float2bfloat16(v.z));
        float h3 = __bfloat162float(__float2bfloat16(v.w));
        int idx = r * AST + h4 * 2;
        *reinterpret_cast<uint2*>(smu + QH_OFF + idx) =
            make_uint2(pack_bf16(h0, h1), pack_bf16(h2, h3));
        *reinterpret_cast<uint2*>(smu + QL_OFF + idx) =
            make_uint2(pack_bf16(v.x - h0, v.y - h1),
                       pack_bf16(v.z - h2, v.w - h3));
    }
    __syncthreads();

    // ---- hoist Q fragments into registers (reused every KV tile) ----
    uint32_t qah[4][4], qal[4][4];
#pragma unroll
    for (int kc = 0; kc < 4; kc++) {
        const uint32_t* ap = smu + QH_OFF + (m_base + g) * AST + kc * 8 + t4;
        qah[kc][0] = ap[0]; qah[kc][1] = ap[8 * AST];
        qah[kc][2] = ap[4]; qah[kc][3] = ap[8 * AST + 4];
        const uint32_t* ap2 = smu + QL_OFF + (m_base + g) * AST + kc * 8 + t4;
        qal[kc][0] = ap2[0]; qal[kc][1] = ap2[8 * AST];
        qal[kc][2] = ap2[4]; qal[kc][3] = ap2[8 * AST + 4];
    }

    float m0 = -1e30f, m1 = -1e30f, l0 = 0.f, l1 = 0.f;
    float oacc[8][4];
#pragma unroll
    for (int nt = 0; nt < 8; nt++)
#pragma unroll
        for (int e = 0; e < 4; e++) oacc[nt][e] = 0.f;

    __nv_bfloat16* vh16 = reinterpret_cast<__nv_bfloat16*>(smu + VH_OFF);
    __nv_bfloat16* vl16 = reinterpret_cast<__nv_bfloat16*>(smu + VL_OFF);

    const int ntiles = qt + 1;
    for (int st = 0; st < ntiles; st++) {
        const int s0 = st * 64;
        const float* kg = g_k + ((size_t)b * NT + s0) * NH;
        const float* vg = g_v + ((size_t)b * NT + s0) * NH;

        __syncthreads();  // prior iteration's fragment reads done
        // ---- K tile [j][h] and V tile transposed [h][s], bf16 hi/lo ----
#pragma unroll
        for (int it = 0; it < 8; it++) {
            int f4 = tid + it * 128;
            int r = f4 >> 4;           // j / s index
            int h4 = f4 & 15;
            float4 kv = *reinterpret_cast<const float4*>(&kg[r * NH + h4 * 4]);
            float h0 = __bfloat162float(__float2bfloat16(kv.x));
            float h1 = __bfloat162float(__float2bfloat16(kv.y));
            float h2 = __bfloat162float(__float2bfloat16(kv.z));
            float h3 = __bfloat162float(__float2bfloat16(kv.w));
            int idx = r * AST + h4 * 2;
            *reinterpret_cast<uint2*>(smu + KH_OFF + idx) =
                make_uint2(pack_bf16(h0, h1), pack_bf16(h2, h3));
            *reinterpret_cast<uint2*>(smu + KL_OFF + idx) =
                make_uint2(pack_bf16(kv.x - h0, kv.y - h1),
                           pack_bf16(kv.z - h2, kv.w - h3));

            float4 vv = *reinterpret_cast<const float4*>(&vg[r * NH + h4 * 4]);
            float vvv[4] = {vv.x, vv.y, vv.z, vv.w};
#pragma unroll
            for (int c = 0; c < 4; c++) {
                int h = h4 * 4 + c;
                __nv_bfloat16 hi = __float2bfloat16(vvv[c]);
                vh16[h * (AST * 2) + r] = hi;
                vl16[h * (AST * 2) + r] =
                    __float2bfloat16(vvv[c] - __bfloat162float(hi));
            }
        }
        __syncthreads();

        // ---- S = Q K^T (split bf16, 3 MMAs) ----
        float sacc[8][4];
#pragma unroll
        for (int nt = 0; nt < 8; nt++)
#pragma unroll
            for (int e = 0; e < 4; e++) sacc[nt][e] = 0.f;

#pragma unroll
        for (int kc = 0; kc < 4; kc++) {
#pragma unroll
            for (int nt = 0; nt < 8; nt++) {
                const uint32_t* bp = smu + KH_OFF + (nt * 8 + g) * AST + kc * 8 + t4;
                uint32_t bh0 = bp[0], bh1 = bp[4];
                const uint32_t* bp2 = smu + KL_OFF + (nt * 8 + g) * AST + kc * 8 + t4;
                uint32_t bl0 = bp2[0], bl1 = bp2[4];
                MMA_BF16(sacc[nt], qah[kc][0], qah[kc][1], qah[kc][2], qah[kc][3], bh0, bh1);
                MMA_BF16(sacc[nt], qah[kc][0], qah[kc][1], qah[kc][2], qah[kc][3], bl0, bl1);
                MMA_BF16(sacc[nt], qal[kc][0], qal[kc][1], qal[kc][2], qal[kc][3], bh0, bh1);
            }
        }

        // ---- scale + causal mask (diag tile only) ----
        const bool diag = (st == qt);
#pragma unroll
        for (int nt = 0; nt < 8; nt++) {
#pragma unroll
            for (int e = 0; e < 4; e++) {
                int col = nt * 8 + 2 * t4 + (e & 1);
                int row = m_base + g + ((e >= 2) ? 8 : 0);
                float v = sacc[nt][e] * 0.125f;
                if (diag && (col > row)) v = -1e30f;
                sacc[nt][e] = v;
            }
        }

        // ---- register softmax (rows g and g+8; reduce over 4-lane group) ----
        float mx0 = -1e30f, mx1 = -1e30f;
#pragma unroll
        for (int nt = 0; nt < 8; nt++) {
            mx0 = fmaxf(mx0, fmaxf(sacc[nt][0], sacc[nt][1]));
            mx1 = fmaxf(mx1, fmaxf(sacc[nt][2], sacc[nt][3]));
        }
        mx0 = fmaxf(mx0, __shfl_xor_sync(0xffffffffu, mx0, 1));
        mx0 = fmaxf(mx0, __shfl_xor_sync(0xffffffffu, mx0, 2));
        mx1 = fmaxf(mx1, __shfl_xor_sync(0xffffffffu, mx1, 1));
        mx1 = fmaxf(mx1, __shfl_xor_sync(0xffffffffu, mx1, 2));
        float nm0 = fmaxf(m0, mx0), nm1 = fmaxf(m1, mx1);
        float c0 = __expf(m0 - nm0), c1 = __expf(m1 - nm1);
        m0 = nm0; m1 = nm1;
        float sum0 = 0.f, sum1 = 0.f;
#pragma unroll
        for (int nt = 0; nt < 8; nt++) {
            float p0 = __expf(sacc[nt][0] - nm0);
            float p1 = __expf(sacc[nt][1] - nm0);
            float p2 = __expf(sacc[nt][2] - nm1);
            float p3 = __expf(sacc[nt][3] - nm1);
            sacc[nt][0] = p0; sacc[nt][1] = p1;
            sacc[nt][2] = p2; sacc[nt][3] = p3;
            sum0 += p0 + p1; sum1 += p2 + p3;
        }
        sum0 += __shfl_xor_sync(0xffffffffu, sum0, 1);
        sum0 += __shfl_xor_sync(0xffffffffu, sum0, 2);
        sum1 += __shfl_xor_sync(0xffffffffu, sum1, 1);
        sum1 += __shfl_xor_sync(0xffffffffu, sum1, 2);
        l0 = l0 * c0 + sum0;
        l1 = l1 * c1 + sum1;
#pragma unroll
        for (int nt = 0; nt < 8; nt++) {
            oacc[nt][0] *= c0; oacc[nt][1] *= c0;
            oacc[nt][2] *= c1; oacc[nt][3] *= c1;
        }

        // ---- O += P V (P in registers; split bf16, 3 MMAs) ----
#pragma unroll
        for (int kc = 0; kc < 4; kc++) {
            float p00 = sacc[2 * kc][0],     p01 = sacc[2 * kc][1];
            float p02 = sacc[2 * kc][2],     p03 = sacc[2 * kc][3];
            float p10 = sacc[2 * kc + 1][0], p11 = sacc[2 * kc + 1][1];
            float p12 = sacc[2 * kc + 1][2], p13 = sacc[2 * kc + 1][3];
            uint32_t pa0 = pack_bf16(p00, p01);
            uint32_t pa1 = pack_bf16(p02, p03);
            uint32_t pa2 = pack_bf16(p10, p11);
            uint32_t pa3 = pack_bf16(p12, p13);
            // residuals
            float r00 = p00 - __bfloat162float(__float2bfloat16(p00));
            float r01 = p01 - __bfloat162float(__float2bfloat16(p01));
            float r02 = p02 - __bfloat162float(__float2bfloat16(p02));
            float r03 = p03 - __bfloat162float(__float2bfloat16(p03));
            float r10 = p10 - __bfloat162float(__float2bfloat16(p10));
            float r11 = p11 - __bfloat162float(__float2bfloat16(p11));
            float r12 = p12 - __bfloat162float(__float2bfloat16(p12));
            float r13 = p13 - __bfloat162float(__float2bfloat16(p13));
            uint32_t pl0 = pack_bf16(r00, r01);
            uint32_t pl1 = pack_bf16(r02, r03);
            uint32_t pl2 = pack_bf16(r10, r11);
            uint32_t pl3 = pack_bf16(r12, r13);
#pragma unroll
            for (int nt = 0; nt < 8; nt++) {
                const uint32_t* vp = smu + VH_OFF + (nt * 8 + g) * AST + kc * 8 + t4;
                uint32_t vb0 = vp[0], vb1 = vp[4];
                const uint32_t* vp2 = smu + VL_OFF + (nt * 8 + g) * AST + kc * 8 + t4;
                uint32_t vl0 = vp2[0], vl1 = vp2[4];
                MMA_BF16(oacc[nt], pa0, pa1, pa2, pa3, vb0, vb1);
                MMA_BF16(oacc[nt], pa0, pa1, pa2, pa3, vl0, vl1);
                MMA_BF16(oacc[nt], pl0, pl1, pl2, pl3, vb0, vb1);
            }
        }
    }

    // ---- epilogue: out = O / l ----
    float inv0 = 1.0f / l0;
    float inv1 = 1.0f / l1;
    size_t row0 = (size_t)b * NT + qs + m_base + g;
    size_t row1 = row0 + 8;
#pragma unroll
    for (int nt = 0; nt < 8; nt++) {
        int col = nt * 8 + 2 * t4;
        *reinterpret_cast<float2*>(&out[row0 * NH + col]) =
            make_float2(oacc[nt][0] * inv0, oacc[nt][1] * inv0);
        *reinterpret_cast<float2*>(&out[row1 * NH + col]) =
            make_float2(oacc[nt][2] * inv1, oacc[nt][3] * inv1);
    }
}

// ===========================================================================
extern "C" void kernel_launch(void* const* d_in, const int* in_sizes, int n_in,
                              void* d_out, int out_size)
{
    const float* x  = (const float*)d_in[0];
    const float* wq = (const float*)d_in[1];
    const float* wk = (const float*)d_in[2];
    const float* wv = (const float*)d_in[3];
    float* out = (float*)d_out;

    cudaFuncSetAttribute(qkv_mma_kernel,
                         cudaFuncAttributeMaxDynamicSharedMemorySize,
                         QKV_SMEM_BYTES);
    qkv_mma_kernel<<<dim3(256, 2), 256, QKV_SMEM_BYTES>>>(x, wq, wk, wv);

    cudaFuncSetAttribute(attn_mma_kernel,
                         cudaFuncAttributeMaxDynamicSharedMemorySize,
                         ATTN_SMEM_BYTES);
    attn_mma_kernel<<<dim3(NT / 64, NB), 128, ATTN_SMEM_BYTES>>>(out);
}

// round 8
// speedup vs baseline: 2.1386x; 1.0752x over previous
#include <cuda_runtime.h>
#include <cuda_bf16.h>
#include <math.h>
#include <stdint.h>

#define NB 16
#define NT 2048
#define NC 1024
#define NH 64

// Scratch for Q, K, V projections: [B*T, H] each (8 MB apiece).
__device__ float g_q[NB * NT * NH];
__device__ float g_k[NB * NT * NH];
__device__ float g_v[NB * NT * NH];

__device__ __forceinline__ uint32_t pack_bf16(float a, float b) {
    __nv_bfloat162 t = __floats2bfloat162_rn(a, b);
    return *reinterpret_cast<uint32_t*>(&t);
}

__device__ __forceinline__ uint32_t smem_u32(const void* p) {
    uint32_t a;
    asm("{ .reg .u64 t; cvta.to.shared.u64 t, %1; cvt.u32.u64 %0, t; }"
        : "=r"(a) : "l"(p));
    return a;
}

// mma.sync m16n8k16 bf16 (baseline PTX, works on plain sm_103 target)
#define MMA_BF16(c, a0, a1, a2, a3, b0, b1)                                \
    asm volatile(                                                          \
        "mma.sync.aligned.m16n8k16.row.col.f32.bf16.bf16.f32 "             \
        "{%0,%1,%2,%3}, {%4,%5,%6,%7}, {%8,%9}, {%0,%1,%2,%3};"            \
        : "+f"((c)[0]), "+f"((c)[1]), "+f"((c)[2]), "+f"((c)[3])           \
        : "r"(a0), "r"(a1), "r"(a2), "r"(a3), "r"(b0), "r"(b1))

#define CP_ASYNC16(dst, src) \
    asm volatile("cp.async.cg.shared.global [%0], [%1], 16;" \
        :: "r"(dst), "l"(src) : "memory")
#define CP_COMMIT() asm volatile("cp.async.commit_group;" ::: "memory")
#define CP_WAIT0()  asm volatile("cp.async.wait_group 0;" ::: "memory")

// ===========================================================================
// Kernel 1: fused QKV projection, bf16 split-precision mma.sync. (R4/R5)
// ===========================================================================
#define KST 20
#define A_H_OFF 0
#define A_L_OFF (128 * KST)
#define B_H_OFF (2 * 128 * KST)
#define B_L_OFF (2 * 128 * KST + 96 * KST)
#define QKV_BUF_U32 (2 * 128 * KST + 2 * 96 * KST)
#define QKV_SMEM_BYTES (2 * QKV_BUF_U32 * 4)

__global__ __launch_bounds__(256) void qkv_mma_kernel(
    const float* __restrict__ x,
    const float* __restrict__ wq,
    const float* __restrict__ wk,
    const float* __restrict__ wv)
{
    extern __shared__ char dynsm[];
    uint32_t* smu = reinterpret_cast<uint32_t*>(dynsm);

    const int tid = threadIdx.x;
    const int warp = tid >> 5;
    const int lane = tid & 31;
    const int g = lane >> 2;
    const int t4 = lane & 3;
    const int wm = warp & 3;
    const int wn = warp >> 2;
    const int m_base = wm * 32;
    const int n_base = wn * 48;
    const int row0 = blockIdx.x * 128;
    const int col0 = blockIdx.y * 96;

    float acc[2][6][4];
#pragma unroll
    for (int mt = 0; mt < 2; mt++)
#pragma unroll
        for (int nt = 0; nt < 6; nt++)
#pragma unroll
            for (int i = 0; i < 4; i++) acc[mt][nt][i] = 0.f;

    float4 ast[4];
    float bst[3][4];

    auto ldg_tiles = [&](int k0) {
#pragma unroll
        for (int it = 0; it < 4; it++) {
            int f4 = tid + it * 256;
            int r = f4 >> 3;
            int c4 = f4 & 7;
            ast[it] = *reinterpret_cast<const float4*>(
                &x[(size_t)(row0 + r) * NC + k0 + c4 * 4]);
        }
#pragma unroll
        for (int it = 0; it < 3; it++) {
            int p = tid + it * 256;
            int n_g = p % 96;
            int kp = p / 96;
            int n_global = col0 + n_g;
            int seg = n_global >> 6;
            int nc = n_global & 63;
            const float* wp = (seg == 0) ? wq : (seg == 1) ? wk : wv;
            const float* src = wp + (size_t)(k0 + kp * 4) * NH + nc;
#pragma unroll
            for (int j = 0; j < 4; j++) bst[it][j] = src[j * NH];
        }
    };

    auto sts_tiles = [&](int buf) {
        uint32_t* base = smu + buf * QKV_BUF_U32;
#pragma unroll
        for (int it = 0; it < 4; it++) {
            int f4 = tid + it * 256;
            int r = f4 >> 3;
            int c4 = f4 & 7;
            float4 v = ast[it];
            float h0 = __bfloat162float(__float2bfloat16(v.x));
            float h1 = __bfloat162float(__float2bfloat16(v.y));
            float h2 = __bfloat162float(__float2bfloat16(v.z));
            float h3 = __bfloat162float(__float2bfloat16(v.w));
            int idx = r * KST + c4 * 2;
            base[A_H_OFF + idx + 0] = pack_bf16(h0, h1);
            base[A_H_OFF + idx + 1] = pack_bf16(h2, h3);
            base[A_L_OFF + idx + 0] = pack_bf16(v.x - h0, v.y - h1);
            base[A_L_OFF + idx + 1] = pack_bf16(v.z - h2, v.w - h3);
        }
#pragma unroll
        for (int it = 0; it < 3; it++) {
            int p = tid + it * 256;
            int n_g = p % 96;
            int kp = p / 96;
            float v0 = bst[it][0], v1 = bst[it][1], v2 = bst[it][2], v3 = bst[it][3];
            float h0 = __bfloat162float(__float2bfloat16(v0));
            float h1 = __bfloat162float(__float2bfloat16(v1));
            float h2 = __bfloat162float(__float2bfloat16(v2));
            float h3 = __bfloat162float(__float2bfloat16(v3));
            int idx = n_g * KST + kp * 2;
            base[B_H_OFF + idx + 0] = pack_bf16(h0, h1);
            base[B_H_OFF + idx + 1] = pack_bf16(h2, h3);
            base[B_L_OFF + idx + 0] = pack_bf16(v0 - h0, v1 - h1);
            base[B_L_OFF + idx + 1] = pack_bf16(v2 - h2, v3 - h3);
        }
    };

    auto compute = [&](int buf) {
        uint32_t* base = smu + buf * QKV_BUF_U32;
        const uint32_t* Ah = base + A_H_OFF;
        const uint32_t* Al = base + A_L_OFF;
        const uint32_t* Bh = base + B_H_OFF;
        const uint32_t* Bl = base + B_L_OFF;
#pragma unroll
        for (int ks = 0; ks < 2; ks++) {
            uint32_t bh[6][2], bl[6][2];
#pragma unroll
            for (int nt = 0; nt < 6; nt++) {
                int nrow = n_base + nt * 8 + g;
                const uint32_t* bp = Bh + nrow * KST + ks * 8 + t4;
                bh[nt][0] = bp[0];
                bh[nt][1] = bp[4];
                const uint32_t* bp2 = Bl + nrow * KST + ks * 8 + t4;
                bl[nt][0] = bp2[0];
                bl[nt][1] = bp2[4];
            }
#pragma unroll
            for (int mt = 0; mt < 2; mt++) {
                int arow = m_base + mt * 16 + g;
                const uint32_t* ap = Ah + arow * KST + ks * 8 + t4;
                uint32_t ah0 = ap[0], ah1 = ap[8 * KST], ah2 = ap[4], ah3 = ap[8 * KST + 4];
                const uint32_t* ap2 = Al + arow * KST + ks * 8 + t4;
                uint32_t al0 = ap2[0], al1 = ap2[8 * KST], al2 = ap2[4], al3 = ap2[8 * KST + 4];
#pragma unroll
                for (int nt = 0; nt < 6; nt++) {
                    MMA_BF16(acc[mt][nt], ah0, ah1, ah2, ah3, bh[nt][0], bh[nt][1]);
                    MMA_BF16(acc[mt][nt], ah0, ah1, ah2, ah3, bl[nt][0], bl[nt][1]);
                    MMA_BF16(acc[mt][nt], al0, al1, al2, al3, bh[nt][0], bh[nt][1]);
                }
            }
        }
    };

    ldg_tiles(0);
    sts_tiles(0);
    __syncthreads();
    const int NIT = NC / 32;
    for (int tI = 0; tI < NIT; tI++) {
        if (tI + 1 < NIT) ldg_tiles((tI + 1) * 32);
        compute(tI & 1);
        if (tI + 1 < NIT) sts_tiles((tI + 1) & 1);
        __syncthreads();
    }

#pragma unroll
    for (int mt = 0; mt < 2; mt++) {
#pragma unroll
        for (int nt = 0; nt < 6; nt++) {
            int n_global = col0 + n_base + nt * 8 + t4 * 2;
            int seg = n_global >> 6;
            int nc = n_global & 63;
            float* dstb = (seg == 0) ? g_q : (seg == 1) ? g_k : g_v;
            size_t r0 = (size_t)row0 + m_base + mt * 16 + g;
            *reinterpret_cast<float2*>(&dstb[r0 * NH + nc]) =
                make_float2(acc[mt][nt][0], acc[mt][nt][1]);
            *reinterpret_cast<float2*>(&dstb[(r0 + 8) * NH + nc]) =
                make_float2(acc[mt][nt][2], acc[mt][nt][3]);
        }
    }
}

// ===========================================================================
// Kernel 2: causal flash attention, mma.sync bf16 split, BM=128, BN=64.
// 8 warps; warp owns 16 rows. cp.async prefetch of raw fp32 K/V tiles into
// a single staging buffer, converted to bf16 hi/lo each iter; gmem latency
// hidden behind MMA compute of the previous tile.
// ===========================================================================
#define AST 36                       // u32 stride per 64-elem bf16 row
#define RKST 68                      // raw fp32 row stride (floats)
#define QH_OFF 0
#define QL_OFF (128 * AST)           // 4608
#define KH_OFF (2 * 128 * AST)       // 9216
#define KL_OFF (KH_OFF + 64 * AST)
#define VH_OFF (KH_OFF + 2 * 64 * AST)
#define VL_OFF (KH_OFF + 3 * 64 * AST)
#define RAWK_OFF (KH_OFF + 4 * 64 * AST)       // 18432 (x4 = 73728B, 16B-mult)
#define RAWV_OFF (RAWK_OFF + 64 * RKST)        // 22784
#define ATTN_SMEM_U32 (RAWV_OFF + 64 * RKST)   // 27136
#define ATTN_SMEM_BYTES (ATTN_SMEM_U32 * 4)    // 108544

__global__ __launch_bounds__(256) void attn_mma_kernel(float* __restrict__ out)
{
    extern __shared__ char dynsm[];
    uint32_t* smu = reinterpret_cast<uint32_t*>(dynsm);
    float* smf = reinterpret_cast<float*>(dynsm);
    const uint32_t smbase = smem_u32(dynsm);

    const int tid = threadIdx.x;
    const int warp = tid >> 5;
    const int lane = tid & 31;
    const int g = lane >> 2;
    const int t4 = lane & 3;
    const int m_base = warp * 16;
    const int b = blockIdx.y;
    const int qt = gridDim.x - 1 - blockIdx.x;   // heavy tiles first
    const int qs = qt * 128;
    const int ntiles = 2 * qt + 2;

    const float* kg_base = g_k + ((size_t)b * NT) * NH;
    const float* vg_base = g_v + ((size_t)b * NT) * NH;

    // ---- issue cp.async for tile 0 ----
    {
        const float* kg = kg_base;      // s0 = 0
        const float* vg = vg_base;
#pragma unroll
        for (int it = 0; it < 4; it++) {
            int c = tid + it * 256;
            int j = c >> 4;
            int c4 = c & 15;
            CP_ASYNC16(smbase + (RAWK_OFF + j * RKST + c4 * 4) * 4,
                       kg + j * NH + c4 * 4);
            CP_ASYNC16(smbase + (RAWV_OFF + j * RKST + c4 * 4) * 4,
                       vg + j * NH + c4 * 4);
        }
        CP_COMMIT();
    }

    // ---- load Q tile -> smem (bf16 hi/lo, [i][h]) while tile 0 is in flight
    const float* qg = g_q + ((size_t)b * NT + qs) * NH;
#pragma unroll
    for (int it = 0; it < 8; it++) {
        int f4 = tid + it * 256;
        int r = f4 >> 4;
        int h4 = f4 & 15;
        float4 v = *reinterpret_cast<const float4*>(&qg[r * NH + h4 * 4]);
        float h0 = __bfloat162float(__float2bfloat16(v.x));
        float h1 = __bfloat162float(__float2bfloat16(v.y));
        float h2 = __bfloat162float(__float2bfloat16(v.z));
        float h3 = __bfloat162float(__float2bfloat16(v.w));
        int idx = r * AST + h4 * 2;
        *reinterpret_cast<uint2*>(smu + QH_OFF + idx) =
            make_uint2(pack_bf16(h0, h1), pack_bf16(h2, h3));
        *reinterpret_cast<uint2*>(smu + QL_OFF + idx) =
            make_uint2(pack_bf16(v.x - h0, v.y - h1),
                       pack_bf16(v.z - h2, v.w - h3));
    }
    __syncthreads();

    // ---- hoist Q fragments into registers ----
    uint32_t qah[4][4], qal[4][4];
#pragma unroll
    for (int kc = 0; kc < 4; kc++) {
        const uint32_t* ap = smu + QH_OFF + (m_base + g) * AST + kc * 8 + t4;
        qah[kc][0] = ap[0]; qah[kc][1] = ap[8 * AST];
        qah[kc][2] = ap[4]; qah[kc][3] = ap[8 * AST + 4];
        const uint32_t* ap2 = smu + QL_OFF + (m_base + g) * AST + kc * 8 + t4;
        qal[kc][0] = ap2[0]; qal[kc][1] = ap2[8 * AST];
        qal[kc][2] = ap2[4]; qal[kc][3] = ap2[8 * AST + 4];
    }

    float m0 = -1e30f, m1 = -1e30f, l0 = 0.f, l1 = 0.f;
    float oacc[8][4];
#pragma unroll
    for (int nt = 0; nt < 8; nt++)
#pragma unroll
        for (int e = 0; e < 4; e++) oacc[nt][e] = 0.f;

    for (int st = 0; st < ntiles; st++) {
        const int s0 = st * 64;

        CP_WAIT0();
        __syncthreads();   // raw tile st ready; compute st-1 done everywhere

        // ---- convert raw fp32 K/V -> bf16 hi/lo smem ----
        // K: [j][h] pairs along h.  1024 tasks (64j x 16h4), 4 per thread.
#pragma unroll
        for (int it = 0; it < 4; it++) {
            int t = tid + it * 256;
            int j = t >> 4;
            int h4 = t & 15;
            float4 kv = *reinterpret_cast<const float4*>(
                smf + RAWK_OFF + j * RKST + h4 * 4);
            float h0 = __bfloat162float(__float2bfloat16(kv.x));
            float h1 = __bfloat162float(__float2bfloat16(kv.y));
            float h2 = __bfloat162float(__float2bfloat16(kv.z));
            float h3 = __bfloat162float(__float2bfloat16(kv.w));
            int idx = j * AST + h4 * 2;
            *reinterpret_cast<uint2*>(smu + KH_OFF + idx) =
                make_uint2(pack_bf16(h0, h1), pack_bf16(h2, h3));
            *reinterpret_cast<uint2*>(smu + KL_OFF + idx) =
                make_uint2(pack_bf16(kv.x - h0, kv.y - h1),
                           pack_bf16(kv.z - h2, kv.w - h3));
        }
        // V: transpose to [h][s-pairs]. 512 tasks (16h4 x 32s2), 2 per thread.
#pragma unroll
        for (int it = 0; it < 2; it++) {
            int t = tid + it * 256;
            int h4 = t >> 5;
            int s2 = t & 31;
            float4 va = *reinterpret_cast<const float4*>(
                smf + RAWV_OFF + (2 * s2) * RKST + h4 * 4);
            float4 vb = *reinterpret_cast<const float4*>(
                smf + RAWV_OFF + (2 * s2 + 1) * RKST + h4 * 4);
            float aa[4] = {va.x, va.y, va.z, va.w};
            float bb[4] = {vb.x, vb.y, vb.z, vb.w};
#pragma unroll
            for (int c = 0; c < 4; c++) {
                int h = h4 * 4 + c;
                float ha = __bfloat162float(__float2bfloat16(aa[c]));
                float hb = __bfloat162float(__float2bfloat16(bb[c]));
                smu[VH_OFF + h * AST + s2] = pack_bf16(ha, hb);
                smu[VL_OFF + h * AST + s2] =
                    pack_bf16(aa[c] - ha, bb[c] - hb);
            }
        }
        __syncthreads();   // bf16 tiles ready; raw buffer now free

        // ---- prefetch next tile ----
        if (st + 1 < ntiles) {
            const float* kg = kg_base + (size_t)(s0 + 64) * NH;
            const float* vg = vg_base + (size_t)(s0 + 64) * NH;
#pragma unroll
            for (int it = 0; it < 4; it++) {
                int c = tid + it * 256;
                int j = c >> 4;
                int c4 = c & 15;
                CP_ASYNC16(smbase + (RAWK_OFF + j * RKST + c4 * 4) * 4,
                           kg + j * NH + c4 * 4);
                CP_ASYNC16(smbase + (RAWV_OFF + j * RKST + c4 * 4) * 4,
                           vg + j * NH + c4 * 4);
            }
            CP_COMMIT();
        }

        // ---- fully-masked tile for this warp? (rows < all cols) ----
        if (s0 > qs + m_base + 15) continue;   // barriers already passed

        // ---- S = Q K^T (split bf16, 3 MMAs) ----
        float sacc[8][4];
#pragma unroll
        for (int nt = 0; nt < 8; nt++)
#pragma unroll
            for (int e = 0; e < 4; e++) sacc[nt][e] = 0.f;

#pragma unroll
        for (int kc = 0; kc < 4; kc++) {
#pragma unroll
            for (int nt = 0; nt < 8; nt++) {
                const uint32_t* bp = smu + KH_OFF + (nt * 8 + g) * AST + kc * 8 + t4;
                uint32_t bh0 = bp[0], bh1 = bp[4];
                const uint32_t* bp2 = smu + KL_OFF + (nt * 8 + g) * AST + kc * 8 + t4;
                uint32_t bl0 = bp2[0], bl1 = bp2[4];
                MMA_BF16(sacc[nt], qah[kc][0], qah[kc][1], qah[kc][2], qah[kc][3], bh0, bh1);
                MMA_BF16(sacc[nt], qah[kc][0], qah[kc][1], qah[kc][2], qah[kc][3], bl0, bl1);
                MMA_BF16(sacc[nt], qal[kc][0], qal[kc][1], qal[kc][2], qal[kc][3], bh0, bh1);
            }
        }

        // ---- scale + causal mask ----
        const bool maskzone = (s0 + 63 > qs + m_base);
        if (maskzone) {
#pragma unroll
            for (int nt = 0; nt < 8; nt++) {
#pragma unroll
                for (int e = 0; e < 4; e++) {
                    int col = s0 + nt * 8 + 2 * t4 + (e & 1);
                    int row = qs + m_base + g + ((e >= 2) ? 8 : 0);
                    float v = sacc[nt][e] * 0.125f;
                    sacc[nt][e] = (col > row) ? -1e30f : v;
                }
            }
        } else {
#pragma unroll
            for (int nt = 0; nt < 8; nt++)
#pragma unroll
                for (int e = 0; e < 4; e++) sacc[nt][e] *= 0.125f;
        }

        // ---- register softmax (rows g, g+8; reduce over 4-lane group) ----
        float mx0 = -1e30f, mx1 = -1e30f;
#pragma unroll
        for (int nt = 0; nt < 8; nt++) {
            mx0 = fmaxf(mx0, fmaxf(sacc[nt][0], sacc[nt][1]));
            mx1 = fmaxf(mx1, fmaxf(sacc[nt][2], sacc[nt][3]));
        }
        mx0 = fmaxf(mx0, __shfl_xor_sync(0xffffffffu, mx0, 1));
        mx0 = fmaxf(mx0, __shfl_xor_sync(0xffffffffu, mx0, 2));
        mx1 = fmaxf(mx1, __shfl_xor_sync(0xffffffffu, mx1, 1));
        mx1 = fmaxf(mx1, __shfl_xor_sync(0xffffffffu, mx1, 2));
        float nm0 = fmaxf(m0, mx0), nm1 = fmaxf(m1, mx1);
        float c0 = __expf(m0 - nm0), c1 = __expf(m1 - nm1);
        m0 = nm0; m1 = nm1;
        float sum0 = 0.f, sum1 = 0.f;
#pragma unroll
        for (int nt = 0; nt < 8; nt++) {
            float p0 = __expf(sacc[nt][0] - nm0);
            float p1 = __expf(sacc[nt][1] - nm0);
            float p2 = __expf(sacc[nt][2] - nm1);
            float p3 = __expf(sacc[nt][3] - nm1);
            sacc[nt][0] = p0; sacc[nt][1] = p1;
            sacc[nt][2] = p2; sacc[nt][3] = p3;
            sum0 += p0 + p1; sum1 += p2 + p3;
        }
        sum0 += __shfl_xor_sync(0xffffffffu, sum0, 1);
        sum0 += __shfl_xor_sync(0xffffffffu, sum0, 2);
        sum1 += __shfl_xor_sync(0xffffffffu, sum1, 1);
        sum1 += __shfl_xor_sync(0xffffffffu, sum1, 2);
        l0 = l0 * c0 + sum0;
        l1 = l1 * c1 + sum1;
#pragma unroll
        for (int nt = 0; nt < 8; nt++) {
            oacc[nt][0] *= c0; oacc[nt][1] *= c0;
            oacc[nt][2] *= c1; oacc[nt][3] *= c1;
        }

        // ---- O += P V (P in registers; split bf16, 3 MMAs) ----
#pragma unroll
        for (int kc = 0; kc < 4; kc++) {
            float p00 = sacc[2 * kc][0],     p01 = sacc[2 * kc][1];
            float p02 = sacc[2 * kc][2],     p03 = sacc[2 * kc][3];
            float p10 = sacc[2 * kc + 1][0], p11 = sacc[2 * kc + 1][1];
            float p12 = sacc[2 * kc + 1][2], p13 = sacc[2 * kc + 1][3];
            uint32_t pa0 = pack_bf16(p00, p01);
            uint32_t pa1 = pack_bf16(p02, p03);
            uint32_t pa2 = pack_bf16(p10, p11);
            uint32_t pa3 = pack_bf16(p12, p13);
            float r00 = p00 - __bfloat162float(__float2bfloat16(p00));
            float r01 = p01 - __bfloat162float(__float2bfloat16(p01));
            float r02 = p02 - __bfloat162float(__float2bfloat16(p02));
            float r03 = p03 - __bfloat162float(__float2bfloat16(p03));
            float r10 = p10 - __bfloat162float(__float2bfloat16(p10));
            float r11 = p11 - __bfloat162float(__float2bfloat16(p11));
            float r12 = p12 - __bfloat162float(__float2bfloat16(p12));
            float r13 = p13 - __bfloat162float(__float2bfloat16(p13));
            uint32_t pl0 = pack_bf16(r00, r01);
            uint32_t pl1 = pack_bf16(r02, r03);
            uint32_t pl2 = pack_bf16(r10, r11);
            uint32_t pl3 = pack_bf16(r12, r13);
#pragma unroll
            for (int nt = 0; nt < 8; nt++) {
                const uint32_t* vp = smu + VH_OFF + (nt * 8 + g) * AST + kc * 8 + t4;
                uint32_t vb0 = vp[0], vb1 = vp[4];
                const uint32_t* vp2 = smu + VL_OFF + (nt * 8 + g) * AST + kc * 8 + t4;
                uint32_t vl0 = vp2[0], vl1 = vp2[4];
                MMA_BF16(oacc[nt], pa0, pa1, pa2, pa3, vb0, vb1);
                MMA_BF16(oacc[nt], pa0, pa1, pa2, pa3, vl0, vl1);
                MMA_BF16(oacc[nt], pl0, pl1, pl2, pl3, vb0, vb1);
            }
        }
    }

    // ---- epilogue: out = O / l ----
    float inv0 = 1.0f / l0;
    float inv1 = 1.0f / l1;
    size_t row0 = (size_t)b * NT + qs + m_base + g;
    size_t row1 = row0 + 8;
#pragma unroll
    for (int nt = 0; nt < 8; nt++) {
        int col = nt * 8 + 2 * t4;
        *reinterpret_cast<float2*>(&out[row0 * NH + col]) =
            make_float2(oacc[nt][0] * inv0, oacc[nt][1] * inv0);
        *reinterpret_cast<float2*>(&out[row1 * NH + col]) =
            make_float2(oacc[nt][2] * inv1, oacc[nt][3] * inv1);
    }
}

// ===========================================================================
extern "C" void kernel_launch(void* const* d_in, const int* in_sizes, int n_in,
                              void* d_out, int out_size)
{
    const float* x  = (const float*)d_in[0];
    const float* wq = (const float*)d_in[1];
    const float* wk = (const float*)d_in[2];
    const float* wv = (const float*)d_in[3];
    float* out = (float*)d_out;

    cudaFuncSetAttribute(qkv_mma_kernel,
                         cudaFuncAttributeMaxDynamicSharedMemorySize,
                         QKV_SMEM_BYTES);
    qkv_mma_kernel<<<dim3(256, 2), 256, QKV_SMEM_BYTES>>>(x, wq, wk, wv);

    cudaFuncSetAttribute(attn_mma_kernel,
                         cudaFuncAttributeMaxDynamicSharedMemorySize,
                         ATTN_SMEM_BYTES);
    attn_mma_kernel<<<dim3(NT / 128, NB), 256, ATTN_SMEM_BYTES>>>(out);
}

// round 13
// speedup vs baseline: 2.4444x; 1.1430x over previous
#include <cuda_runtime.h>
#include <cuda_bf16.h>
#include <math.h>
#include <stdint.h>

#define NB 16
#define NT 2048
#define NC 1024
#define NH 64

// Q projection fp32; K/V pre-split bf16 (hi/lo) in MMA-ready layouts.
__device__ float    g_q[NB * NT * NH];
__device__ uint32_t g_kh4[NB * NT * (NH / 2)];          // [row][h-pair]
__device__ uint32_t g_kl4[NB * NT * (NH / 2)];
__device__ uint32_t g_vh4[NB * 32 * NH * 32];           // [b][tile][h][s-pair]
__device__ uint32_t g_vl4[NB * 32 * NH * 32];
// Pre-split weights, [n:192][k-pair:512] (cp.async-ready, row = 1024B)
__device__ uint32_t g_wh4[192 * 512];
__device__ uint32_t g_wl4[192 * 512];

__device__ __forceinline__ uint32_t pack_bf16(float a, float b) {
    __nv_bfloat162 t = __floats2bfloat162_rn(a, b);
    return *reinterpret_cast<uint32_t*>(&t);
}

// rn hi/lo split of a float pair
__device__ __forceinline__ void split_pair(float x0, float x1,
                                           uint32_t& hp, uint32_t& lp) {
    hp = pack_bf16(x0, x1);
    float h0 = __uint_as_float(hp << 16);
    float h1 = __uint_as_float(hp & 0xFFFF0000u);
    lp = pack_bf16(x0 - h0, x1 - h1);
}

__device__ __forceinline__ uint32_t smem_u32(const void* p) {
    uint32_t a;
    asm("{ .reg .u64 t; cvta.to.shared.u64 t, %1; cvt.u32.u64 %0, t; }"
        : "=r"(a) : "l"(p));
    return a;
}

__device__ __forceinline__ float ex2f(float x) {
    float r;
    asm("ex2.approx.ftz.f32 %0, %1;" : "=f"(r) : "f"(x));
    return r;
}

#define MMA_BF16(c, a0, a1, a2, a3, b0, b1)                                \
    asm volatile(                                                          \
        "mma.sync.aligned.m16n8k16.row.col.f32.bf16.bf16.f32 "             \
        "{%0,%1,%2,%3}, {%4,%5,%6,%7}, {%8,%9}, {%0,%1,%2,%3};"            \
        : "+f"((c)[0]), "+f"((c)[1]), "+f"((c)[2]), "+f"((c)[3])           \
        : "r"(a0), "r"(a1), "r"(a2), "r"(a3), "r"(b0), "r"(b1))

#define CP_ASYNC16(dst, src) \
    asm volatile("cp.async.cg.shared.global [%0], [%1], 16;" \
        :: "r"(dst), "l"(src) : "memory")
#define CP_COMMIT() asm volatile("cp.async.commit_group;" ::: "memory")
#define CP_WAIT0()  asm volatile("cp.async.wait_group 0;" ::: "memory")

// ===========================================================================
// Kernel 0: split weights -> bf16 hi/lo, [n][k] layout. Run once, tiny.
// ===========================================================================
__global__ __launch_bounds__(256) void split_w_kernel(
    const float* __restrict__ wq,
    const float* __restrict__ wk,
    const float* __restrict__ wv)
{
    const int n = blockIdx.x;          // 0..191
    const int seg = n >> 6;
    const int nc = n & 63;
    const float* wp = (seg == 0) ? wq : (seg == 1) ? wk : wv;
    for (int kp = threadIdx.x; kp < 512; kp += 256) {
        float v0 = wp[(size_t)(2 * kp) * NH + nc];
        float v1 = wp[(size_t)(2 * kp + 1) * NH + nc];
        uint32_t hp, lp;
        split_pair(v0, v1, hp, lp);
        g_wh4[n * 512 + kp] = hp;
        g_wl4[n * 512 + kp] = lp;
    }
}

// ===========================================================================
// Kernel 1: fused QKV projection. M=128, N=96, grid (256,2), 256 threads.
// w via cp.async from pre-split; x via cp.async raw fp32, A-frags built
// per-warp in registers. Epilogue writes Q fp32, K split bf16, V split
// bf16 TRANSPOSED per 64-seq-tile (smem bounce).
// ===========================================================================
#define WST 20                       // u32 stride per w row (16 used)
#define XRST 36                      // float stride per raw x row (32 used)
#define W_OFF 0                      // 2 bufs x (hi 96*20 + lo 96*20) = 7680
#define W_BUF 3840
#define W_LO 1920
#define XRAW_OFF 7680                // 2 bufs x 128*36 = 9216
#define XRAW_BUF 4608
#define QKV_SMEM_U32 (7680 + 9216)   // 16896 u32 = 67584 B
#define QKV_SMEM_BYTES (QKV_SMEM_U32 * 4)
#define VBST 65                      // vbuf fp32 stride (reuses XRAW region)

__global__ __launch_bounds__(256) void qkv_mma_kernel(
    const float* __restrict__ x)
{
    extern __shared__ char dynsm[];
    uint32_t* smu = reinterpret_cast<uint32_t*>(dynsm);
    float* smf = reinterpret_cast<float*>(dynsm);
    const uint32_t smbase = smem_u32(dynsm);

    const int tid = threadIdx.x;
    const int warp = tid >> 5;
    const int lane = tid & 31;
    const int g = lane >> 2;
    const int t4 = lane & 3;
    const int wm = warp & 3;
    const int wn = warp >> 2;
    const int m_base = wm * 32;
    const int n_base = wn * 48;
    const int row0 = blockIdx.x * 128;
    const int col0 = blockIdx.y * 96;

    float acc[2][6][4];
#pragma unroll
    for (int mt = 0; mt < 2; mt++)
#pragma unroll
        for (int nt = 0; nt < 6; nt++)
#pragma unroll
            for (int i = 0; i < 4; i++) acc[mt][nt][i] = 0.f;

    // ---- cp.async one K-slab (w hi/lo + raw x) into buffer b ----
    auto issue_cp = [&](int b, int k0) {
#pragma unroll
        for (int it = 0; it < 3; it++) {
            int p = tid + it * 256;
            int lo = (p >= 384);
            int rem = p - lo * 384;
            int n_l = rem >> 2;
            int c4 = rem & 3;
            const uint32_t* src = (lo ? g_wl4 : g_wh4)
                + (size_t)(col0 + n_l) * 512 + (k0 >> 1) + c4 * 4;
            CP_ASYNC16(smbase + (W_OFF + b * W_BUF + lo * W_LO
                                 + n_l * WST + c4 * 4) * 4, src);
        }
#pragma unroll
        for (int it = 0; it < 4; it++) {
            int p = tid + it * 256;
            int r = p >> 3;
            int c4 = p & 7;
            const float* src = x + (size_t)(row0 + r) * NC + k0 + c4 * 4;
            CP_ASYNC16(smbase + (XRAW_OFF + b * XRAW_BUF
                                 + r * XRST + c4 * 4) * 4, src);
        }
        CP_COMMIT();
    };

    issue_cp(0, 0);

    const int NIT = NC / 32;   // 32
    for (int t = 0; t < NIT; t++) {
        const int b = t & 1;
        CP_WAIT0();
        __syncthreads();
        if (t + 1 < NIT) issue_cp(b ^ 1, (t + 1) * 32);

        const float* raw = smf + XRAW_OFF + b * XRAW_BUF;
        const uint32_t* Bh = smu + W_OFF + b * W_BUF;
        const uint32_t* Bl = Bh + W_LO;

#pragma unroll
        for (int ks = 0; ks < 2; ks++) {
            uint32_t bh[6][2], bl[6][2];
#pragma unroll
            for (int nt = 0; nt < 6; nt++) {
                const uint32_t* bp = Bh + (n_base + nt * 8 + g) * WST + ks * 8 + t4;
                bh[nt][0] = bp[0]; bh[nt][1] = bp[4];
                const uint32_t* bp2 = Bl + (n_base + nt * 8 + g) * WST + ks * 8 + t4;
                bl[nt][0] = bp2[0]; bl[nt][1] = bp2[4];
            }
#pragma unroll
            for (int mt = 0; mt < 2; mt++) {
                int r0 = m_base + mt * 16 + g;
                int c = ks * 16 + t4 * 2;
                float2 v00 = *reinterpret_cast<const float2*>(raw + r0 * XRST + c);
                float2 v10 = *reinterpret_cast<const float2*>(raw + (r0 + 8) * XRST + c);
                float2 v01 = *reinterpret_cast<const float2*>(raw + r0 * XRST + c + 8);
                float2 v11 = *reinterpret_cast<const float2*>(raw + (r0 + 8) * XRST + c + 8);
                uint32_t ah0, ah1, ah2, ah3, al0, al1, al2, al3;
                split_pair(v00.x, v00.y, ah0, al0);
                split_pair(v10.x, v10.y, ah1, al1);
                split_pair(v01.x, v01.y, ah2, al2);
                split_pair(v11.x, v11.y, ah3, al3);
#pragma unroll
                for (int nt = 0; nt < 6; nt++) {
                    MMA_BF16(acc[mt][nt], ah0, ah1, ah2, ah3, bh[nt][0], bh[nt][1]);
                    MMA_BF16(acc[mt][nt], ah0, ah1, ah2, ah3, bl[nt][0], bl[nt][1]);
                    MMA_BF16(acc[mt][nt], al0, al1, al2, al3, bh[nt][0], bh[nt][1]);
                }
            }
        }
        __syncthreads();
    }

    // ---- epilogue: Q fp32 / K split / V to smem bounce ----
    bool has_v = false;
#pragma unroll
    for (int mt = 0; mt < 2; mt++) {
#pragma unroll
        for (int nt = 0; nt < 6; nt++) {
            int n_global = col0 + n_base + nt * 8 + t4 * 2;
            int r0 = m_base + mt * 16 + g;
            if (n_global < 64) {
                size_t gr = (size_t)row0 + r0;
                *reinterpret_cast<float2*>(&g_q[gr * NH + n_global]) =
                    make_float2(acc[mt][nt][0], acc[mt][nt][1]);
                *reinterpret_cast<float2*>(&g_q[(gr + 8) * NH + n_global]) =
                    make_float2(acc[mt][nt][2], acc[mt][nt][3]);
            } else if (n_global < 128) {
                int kc2 = (n_global - 64) >> 1;
                size_t gr = (size_t)row0 + r0;
                uint32_t hp, lp;
                split_pair(acc[mt][nt][0], acc[mt][nt][1], hp, lp);
                g_kh4[gr * 32 + kc2] = hp;
                g_kl4[gr * 32 + kc2] = lp;
                split_pair(acc[mt][nt][2], acc[mt][nt][3], hp, lp);
                g_kh4[(gr + 8) * 32 + kc2] = hp;
                g_kl4[(gr + 8) * 32 + kc2] = lp;
            } else {
                has_v = true;
            }
        }
    }
    if (col0 == 96) {
        __syncthreads();   // main-loop smem reads done everywhere
        float* vbuf = smf + XRAW_OFF;   // [128][VBST]
        if (has_v) {
#pragma unroll
            for (int mt = 0; mt < 2; mt++) {
#pragma unroll
                for (int nt = 0; nt < 6; nt++) {
                    int n_global = col0 + n_base + nt * 8 + t4 * 2;
                    if (n_global < 128) continue;
                    int vc = n_global - 128;
                    int r0 = m_base + mt * 16 + g;
                    vbuf[r0 * VBST + vc] = acc[mt][nt][0];
                    vbuf[r0 * VBST + vc + 1] = acc[mt][nt][1];
                    vbuf[(r0 + 8) * VBST + vc] = acc[mt][nt][2];
                    vbuf[(r0 + 8) * VBST + vc + 1] = acc[mt][nt][3];
                }
            }
        }
        __syncthreads();
        const int bb = row0 >> 11;
        const int st0 = (row0 & 2047) >> 6;
#pragma unroll
        for (int it = 0; it < 16; it++) {
            int idx = tid + it * 256;       // 0..4095
            int s2 = idx & 31;
            int rest = idx >> 5;
            int h = rest & 63;
            int sub = rest >> 6;            // 0..1
            float a = vbuf[(sub * 64 + 2 * s2) * VBST + h];
            float c = vbuf[(sub * 64 + 2 * s2 + 1) * VBST + h];
            uint32_t hp, lp;
            split_pair(a, c, hp, lp);
            size_t dst = ((size_t)(bb * 32 + st0 + sub) * NH + h) * 32 + s2;
            g_vh4[dst] = hp;
            g_vl4[dst] = lp;
        }
    }
}

// ===========================================================================
// Kernel 2: causal flash attention. BM=128, BN=64, 8 warps.
// K/V arrive pre-split via cp.async directly in fragment layout: no convert
// phase, ONE sync per tile. PV uses full 3-MMA split (Ph*Vh + Ph*Vl + Pl*Vh)
// -- the R7-proven precision config. Softmax in base-2.
// ===========================================================================
#define AST 36                        // u32 stride per smem row (32 used)
#define KV_ARR 2304                   // 64 * 36
#define KV_BUF (4 * KV_ARR)           // kh, kl, vh, vl
#define ATTN_SMEM_U32 (2 * KV_BUF)    // 18432 u32 = 73728 B
#define ATTN_SMEM_BYTES (ATTN_SMEM_U32 * 4)
#define SC2 0.1803368801111204f       // 0.125 * log2(e)

__global__ __launch_bounds__(256) void attn_mma_kernel(float* __restrict__ out)
{
    extern __shared__ char dynsm[];
    uint32_t* smu = reinterpret_cast<uint32_t*>(dynsm);
    const uint32_t smbase = smem_u32(dynsm);

    const int tid = threadIdx.x;
    const int warp = tid >> 5;
    const int lane = tid & 31;
    const int g = lane >> 2;
    const int t4 = lane & 3;
    const int m_base = warp * 16;
    const int b = blockIdx.y;
    const int qt = gridDim.x - 1 - blockIdx.x;   // heavy tiles first
    const int qs = qt * 128;
    const int ntiles = 2 * qt + 2;

    // ---- cp.async one pre-split KV tile into buffer ----
    auto issue_cp = [&](int buf, int st) {
#pragma unroll
        for (int it = 0; it < 8; it++) {
            int p = tid + it * 256;        // 0..2047
            int arr = p >> 9;              // 0:kh 1:kl 2:vh 3:vl
            int rem = p & 511;
            int r = rem >> 3;
            int c4 = rem & 7;
            const uint32_t* src;
            if (arr == 0)
                src = g_kh4 + ((size_t)b * NT + st * 64 + r) * 32 + c4 * 4;
            else if (arr == 1)
                src = g_kl4 + ((size_t)b * NT + st * 64 + r) * 32 + c4 * 4;
            else if (arr == 2)
                src = g_vh4 + ((size_t)(b * 32 + st) * NH + r) * 32 + c4 * 4;
            else
                src = g_vl4 + ((size_t)(b * 32 + st) * NH + r) * 32 + c4 * 4;
            CP_ASYNC16(smbase + (buf * KV_BUF + arr * KV_ARR
                                 + r * AST + c4 * 4) * 4, src);
        }
        CP_COMMIT();
    };

    issue_cp(0, 0);

    // ---- build Q fragments straight from gmem (overlaps tile-0 cp) ----
    uint32_t qah[4][4], qal[4][4];
    {
        const float* qg = g_q + ((size_t)b * NT + qs) * NH;
        int r0 = m_base + g;
#pragma unroll
        for (int kc = 0; kc < 4; kc++) {
            int c = kc * 16 + t4 * 2;
            float2 v00 = *reinterpret_cast<const float2*>(qg + (size_t)r0 * NH + c);
            float2 v10 = *reinterpret_cast<const float2*>(qg + (size_t)(r0 + 8) * NH + c);
            float2 v01 = *reinterpret_cast<const float2*>(qg + (size_t)r0 * NH + c + 8);
            float2 v11 = *reinterpret_cast<const float2*>(qg + (size_t)(r0 + 8) * NH + c + 8);
            split_pair(v00.x, v00.y, qah[kc][0], qal[kc][0]);
            split_pair(v10.x, v10.y, qah[kc][1], qal[kc][1]);
            split_pair(v01.x, v01.y, qah[kc][2], qal[kc][2]);
            split_pair(v11.x, v11.y, qah[kc][3], qal[kc][3]);
        }
    }

    float m0 = -1e30f, m1 = -1e30f, l0 = 0.f, l1 = 0.f;
    float oacc[8][4];
#pragma unroll
    for (int nt = 0; nt < 8; nt++)
#pragma unroll
        for (int e = 0; e < 4; e++) oacc[nt][e] = 0.f;

    for (int st = 0; st < ntiles; st++) {
        const int s0 = st * 64;
        const int buf = st & 1;
        CP_WAIT0();
        __syncthreads();
        if (st + 1 < ntiles) issue_cp(buf ^ 1, st + 1);

        // fully-masked for this warp's 16 rows?
        if (s0 > qs + m_base + 15) continue;

        const uint32_t* KH = smu + buf * KV_BUF;
        const uint32_t* KL = KH + KV_ARR;
        const uint32_t* VH = KH + 2 * KV_ARR;
        const uint32_t* VL = KH + 3 * KV_ARR;

        // ---- S = Q K^T (split bf16, 3 MMAs) ----
        float sacc[8][4];
#pragma unroll
        for (int nt = 0; nt < 8; nt++)
#pragma unroll
            for (int e = 0; e < 4; e++) sacc[nt][e] = 0.f;
#pragma unroll
        for (int kc = 0; kc < 4; kc++) {
#pragma unroll
            for (int nt = 0; nt < 8; nt++) {
                const uint32_t* bp = KH + (nt * 8 + g) * AST + kc * 8 + t4;
                uint32_t bh0 = bp[0], bh1 = bp[4];
                const uint32_t* bp2 = KL + (nt * 8 + g) * AST + kc * 8 + t4;
                uint32_t bl0 = bp2[0], bl1 = bp2[4];
                MMA_BF16(sacc[nt], qah[kc][0], qah[kc][1], qah[kc][2], qah[kc][3], bh0, bh1);
                MMA_BF16(sacc[nt], qah[kc][0], qah[kc][1], qah[kc][2], qah[kc][3], bl0, bl1);
                MMA_BF16(sacc[nt], qal[kc][0], qal[kc][1], qal[kc][2], qal[kc][3], bh0, bh1);
            }
        }

        // ---- scale (base-2) + causal mask ----
        const bool maskzone = (s0 + 63 > qs + m_base);
        if (maskzone) {
#pragma unroll
            for (int nt = 0; nt < 8; nt++) {
#pragma unroll
                for (int e = 0; e < 4; e++) {
                    int col = s0 + nt * 8 + 2 * t4 + (e & 1);
                    int row = qs + m_base + g + ((e >= 2) ? 8 : 0);
                    float v = sacc[nt][e] * SC2;
                    sacc[nt][e] = (col > row) ? -1e30f : v;
                }
            }
        } else {
#pragma unroll
            for (int nt = 0; nt < 8; nt++)
#pragma unroll
                for (int e = 0; e < 4; e++) sacc[nt][e] *= SC2;
        }

        // ---- online softmax (base-2), rows g and g+8 ----
        float mx0 = -1e30f, mx1 = -1e30f;
#pragma unroll
        for (int nt = 0; nt < 8; nt++) {
            mx0 = fmaxf(mx0, fmaxf(sacc[nt][0], sacc[nt][1]));
            mx1 = fmaxf(mx1, fmaxf(sacc[nt][2], sacc[nt][3]));
        }
        mx0 = fmaxf(mx0, __shfl_xor_sync(0xffffffffu, mx0, 1));
        mx0 = fmaxf(mx0, __shfl_xor_sync(0xffffffffu, mx0, 2));
        mx1 = fmaxf(mx1, __shfl_xor_sync(0xffffffffu, mx1, 1));
        mx1 = fmaxf(mx1, __shfl_xor_sync(0xffffffffu, mx1, 2));
        float nm0 = fmaxf(m0, mx0), nm1 = fmaxf(m1, mx1);
        float c0 = ex2f(m0 - nm0), c1 = ex2f(m1 - nm1);
        m0 = nm0; m1 = nm1;
        float sum0 = 0.f, sum1 = 0.f;
#pragma unroll
        for (int nt = 0; nt < 8; nt++) {
            float p0 = ex2f(sacc[nt][0] - nm0);
            float p1 = ex2f(sacc[nt][1] - nm0);
            float p2 = ex2f(sacc[nt][2] - nm1);
            float p3 = ex2f(sacc[nt][3] - nm1);
            sacc[nt][0] = p0; sacc[nt][1] = p1;
            sacc[nt][2] = p2; sacc[nt][3] = p3;
            sum0 += p0 + p1; sum1 += p2 + p3;
        }
        sum0 += __shfl_xor_sync(0xffffffffu, sum0, 1);
        sum0 += __shfl_xor_sync(0xffffffffu, sum0, 2);
        sum1 += __shfl_xor_sync(0xffffffffu, sum1, 1);
        sum1 += __shfl_xor_sync(0xffffffffu, sum1, 2);
        l0 = l0 * c0 + sum0;
        l1 = l1 * c1 + sum1;
#pragma unroll
        for (int nt = 0; nt < 8; nt++) {
            oacc[nt][0] *= c0; oacc[nt][1] *= c0;
            oacc[nt][2] *= c1; oacc[nt][3] *= c1;
        }

        // ---- O += P V (P split bf16: Ph*Vh + Ph*Vl + Pl*Vh) ----
#pragma unroll
        for (int kc = 0; kc < 4; kc++) {
            uint32_t pa0, pa1, pa2, pa3, pl0, pl1, pl2, pl3;
            split_pair(sacc[2 * kc][0], sacc[2 * kc][1], pa0, pl0);
            split_pair(sacc[2 * kc][2], sacc[2 * kc][3], pa1, pl1);
            split_pair(sacc[2 * kc + 1][0], sacc[2 * kc + 1][1], pa2, pl2);
            split_pair(sacc[2 * kc + 1][2], sacc[2 * kc + 1][3], pa3, pl3);
#pragma unroll
            for (int nt = 0; nt < 8; nt++) {
                const uint32_t* vp = VH + (nt * 8 + g) * AST + kc * 8 + t4;
                uint32_t vb0 = vp[0], vb1 = vp[4];
                const uint32_t* vp2 = VL + (nt * 8 + g) * AST + kc * 8 + t4;
                uint32_t vl0 = vp2[0], vl1 = vp2[4];
                MMA_BF16(oacc[nt], pa0, pa1, pa2, pa3, vb0, vb1);
                MMA_BF16(oacc[nt], pa0, pa1, pa2, pa3, vl0, vl1);
                MMA_BF16(oacc[nt], pl0, pl1, pl2, pl3, vb0, vb1);
            }
        }
    }

    // ---- epilogue: out = O / l ----
    float inv0 = 1.0f / l0;
    float inv1 = 1.0f / l1;
    size_t row0 = (size_t)b * NT + qs + m_base + g;
    size_t row1 = row0 + 8;
#pragma unroll
    for (int nt = 0; nt < 8; nt++) {
        int col = nt * 8 + 2 * t4;
        *reinterpret_cast<float2*>(&out[row0 * NH + col]) =
            make_float2(oacc[nt][0] * inv0, oacc[nt][1] * inv0);
        *reinterpret_cast<float2*>(&out[row1 * NH + col]) =
            make_float2(oacc[nt][2] * inv1, oacc[nt][3] * inv1);
    }
}

// ===========================================================================
extern "C" void kernel_launch(void* const* d_in, const int* in_sizes, int n_in,
                              void* d_out, int out_size)
{
    const float* x  = (const float*)d_in[0];
    const float* wq = (const float*)d_in[1];
    const float* wk = (const float*)d_in[2];
    const float* wv = (const float*)d_in[3];
    float* out = (float*)d_out;

    split_w_kernel<<<192, 256>>>(wq, wk, wv);

    cudaFuncSetAttribute(qkv_mma_kernel,
                         cudaFuncAttributeMaxDynamicSharedMemorySize,
                         QKV_SMEM_BYTES);
    qkv_mma_kernel<<<dim3(256, 2), 256, QKV_SMEM_BYTES>>>(x);

    cudaFuncSetAttribute(attn_mma_kernel,
                         cudaFuncAttributeMaxDynamicSharedMemorySize,
                         ATTN_SMEM_BYTES);
    attn_mma_kernel<<<dim3(NT / 128, NB), 256, ATTN_SMEM_BYTES>>>(out);
}